// round 15
// baseline (speedup 1.0000x reference)
#include <cuda_runtime.h>
#include <cuda_bf16.h>
#include <math.h>
#include <stdint.h>

#define B_ 16
#define N_ 1025
#define C_ 768
#define H_ 12
#define D_ 64
#define NP_ 1024
#define L_ 256
#define BH_ 192
#define M_ 16400
#define TAUINV 0.125f

// ---------------- scratch (device globals; no runtime allocation) -----------
__device__ float g_q[(size_t)BH_ * N_ * D_];
__device__ float g_k[(size_t)BH_ * N_ * D_];
__device__ float g_v[(size_t)BH_ * N_ * D_];
__device__ float g_y[(size_t)BH_ * N_ * D_];
__device__ float g_qland[(size_t)BH_ * L_ * D_];
__device__ float g_kland[(size_t)BH_ * L_ * D_];
__device__ float g_qn[(size_t)BH_ * NP_];
__device__ float g_kn[(size_t)BH_ * NP_];
__device__ float g_qln[(size_t)BH_ * L_];
__device__ float g_kln[(size_t)BH_ * L_];
__device__ float g_M2[(size_t)BH_ * L_ * L_];
__device__ float g_normv[BH_];
__device__ float g_Vm[(size_t)BH_ * L_ * D_];
__device__ float g_Mcls[(size_t)BH_ * L_];

#define LL_ ((size_t)BH_ * L_ * L_)
__device__ __nv_bfloat16 g_Mh[LL_], g_Ml[LL_];
__device__ __nv_bfloat16 g_T1h[LL_], g_T1l[LL_];
__device__ __nv_bfloat16 g_IhA[LL_], g_IlA[LL_];
__device__ __nv_bfloat16 g_IhB[LL_], g_IlB[LL_];

__device__ __nv_bfloat16 g_M1h[(size_t)BH_ * NP_ * L_], g_M1l[(size_t)BH_ * NP_ * L_];
__device__ __nv_bfloat16 g_M3h[(size_t)BH_ * L_ * NP_], g_M3l[(size_t)BH_ * L_ * NP_];
__device__ __nv_bfloat16 g_qph[(size_t)BH_ * NP_ * D_], g_qpl[(size_t)BH_ * NP_ * D_];
__device__ __nv_bfloat16 g_kph[(size_t)BH_ * NP_ * D_], g_kpl[(size_t)BH_ * NP_ * D_];
__device__ __nv_bfloat16 g_vph[(size_t)BH_ * NP_ * D_], g_vpl[(size_t)BH_ * NP_ * D_];
__device__ __nv_bfloat16 g_qlh[(size_t)BH_ * L_ * D_], g_qll[(size_t)BH_ * L_ * D_];
__device__ __nv_bfloat16 g_klh[(size_t)BH_ * L_ * D_], g_kll[(size_t)BH_ * L_ * D_];
__device__ __nv_bfloat16 g_KVh[(size_t)BH_ * L_ * D_], g_KVl[(size_t)BH_ * L_ * D_];
__device__ __nv_bfloat16 g_Vmh[(size_t)BH_ * L_ * D_], g_Vml[(size_t)BH_ * L_ * D_];

__device__ __nv_bfloat16 g_Xh[(size_t)M_ * C_], g_Xl[(size_t)M_ * C_];
__device__ __nv_bfloat16 g_Wqh[(size_t)3 * C_ * C_], g_Wql[(size_t)3 * C_ * C_];
__device__ __nv_bfloat16 g_Pwh[(size_t)C_ * C_], g_Pwl[(size_t)C_ * C_];
__device__ __nv_bfloat16 g_Yh[(size_t)M_ * C_], g_Yl[(size_t)M_ * C_];

// ======================= warp-MMA helpers ====================================
__device__ __forceinline__ uint32_t smem_u32(const void* p) {
  uint32_t a;
  asm("{ .reg .u64 t; cvta.to.shared.u64 t, %1; cvt.u32.u64 %0, t; }"
      : "=r"(a) : "l"(p));
  return a;
}
__device__ __forceinline__ void ldsm4(uint32_t* r, uint32_t addr) {
  asm volatile(
      "ldmatrix.sync.aligned.m8n8.x4.shared.b16 {%0,%1,%2,%3}, [%4];"
      : "=r"(r[0]), "=r"(r[1]), "=r"(r[2]), "=r"(r[3]) : "r"(addr));
}
__device__ __forceinline__ void ldsm4t(uint32_t* r, uint32_t addr) {
  asm volatile(
      "ldmatrix.sync.aligned.m8n8.x4.trans.shared.b16 {%0,%1,%2,%3}, [%4];"
      : "=r"(r[0]), "=r"(r[1]), "=r"(r[2]), "=r"(r[3]) : "r"(addr));
}
__device__ __forceinline__ void mma16816(float* c, const uint32_t* a,
                                         const uint32_t b0, const uint32_t b1) {
  asm volatile(
      "mma.sync.aligned.m16n8k16.row.col.f32.bf16.bf16.f32 "
      "{%0,%1,%2,%3}, {%4,%5,%6,%7}, {%8,%9}, {%0,%1,%2,%3};"
      : "+f"(c[0]), "+f"(c[1]), "+f"(c[2]), "+f"(c[3])
      : "r"(a[0]), "r"(a[1]), "r"(a[2]), "r"(a[3]), "r"(b0), "r"(b1));
}
__device__ __forceinline__ void split2(float v, __nv_bfloat16& h,
                                       __nv_bfloat16& l) {
  h = __float2bfloat16(v);
  l = __float2bfloat16(v - __bfloat162float(h));
}

// ---------------- generic fp32 -> split-bf16 --------------------------------
__global__ void split_kernel(const float4* __restrict__ in,
                             __nv_bfloat162* __restrict__ h2,
                             __nv_bfloat162* __restrict__ l2, int n4) {
  const int i = blockIdx.x * 256 + threadIdx.x;
  if (i >= n4) return;
  float4 v = in[i];
  __nv_bfloat16 hx, lx, hy, ly;
  split2(v.x, hx, lx);
  split2(v.y, hy, ly);
  __nv_bfloat162 hp, lp;
  hp.x = hx; hp.y = hy; lp.x = lx; lp.y = ly;
  h2[i * 2] = hp;
  l2[i * 2] = lp;
  split2(v.z, hx, lx);
  split2(v.w, hy, ly);
  hp.x = hx; hp.y = hy; lp.x = lx; lp.y = ly;
  h2[i * 2 + 1] = hp;
  l2[i * 2 + 1] = lp;
}

// ---- patch split (warp per row) + optional row sum-of-squares (fused) ------
__global__ void vsplit_norm(const float* __restrict__ src,
                            __nv_bfloat162* __restrict__ vh,
                            __nv_bfloat162* __restrict__ vl,
                            float* __restrict__ norm) {
  const int row = blockIdx.x * 8 + (threadIdx.x >> 5);
  const int lane = threadIdx.x & 31;
  const int bh = row >> 10, r = row & 1023;
  const float2 v = *(const float2*)(src + (size_t)bh * N_ * D_ + D_ +
                                    (size_t)r * D_ + lane * 2);
  __nv_bfloat16 hx, lx, hy, ly;
  split2(v.x, hx, lx);
  split2(v.y, hy, ly);
  __nv_bfloat162 hp, lp;
  hp.x = hx; hp.y = hy; lp.x = lx; lp.y = ly;
  vh[(size_t)row * 32 + lane] = hp;
  vl[(size_t)row * 32 + lane] = lp;
  if (norm) {
    float s = v.x * v.x + v.y * v.y;
#pragma unroll
    for (int o = 16; o; o >>= 1) s += __shfl_xor_sync(0xffffffffu, s, o);
    if (lane == 0) norm[(size_t)bh * NP_ + r] = s;
  }
}

// ---- landmark row norms: one launch for qln and kln ------------------------
__global__ void land_norm() {
  const int bh = blockIdx.x;
  const float* src =
      ((blockIdx.y == 0) ? g_qland : g_kland) + (size_t)bh * L_ * D_;
  float* out = ((blockIdx.y == 0) ? g_qln : g_kln) + (size_t)bh * L_;
  const int w = threadIdx.x >> 5, lane = threadIdx.x & 31;
  for (int r = w; r < L_; r += 8) {
    const float* p = src + (size_t)r * D_;
    float v0 = p[lane], v1 = p[lane + 32];
    float s = v0 * v0 + v1 * v1;
#pragma unroll
    for (int o = 16; o; o >>= 1) s += __shfl_xor_sync(0xffffffffu, s, o);
    if (lane == 0) out[r] = s;
  }
}

// ---------------- y [bh][n][d] -> split bf16 [m][768] (proj A operand) ------
__global__ void ysplit_kernel(__nv_bfloat16* __restrict__ Yh,
                              __nv_bfloat16* __restrict__ Yl) {
  const int m = blockIdx.y;
  const int c = blockIdx.x * 256 + threadIdx.x;
  const int b = m / N_, n = m % N_;
  const int h = c >> 6, d = c & 63;
  const float v = g_y[(((size_t)(b * H_ + h)) * N_ + n) * D_ + d];
  split2(v, Yh[(size_t)m * C_ + c], Yl[(size_t)m * C_ + c]);
}

// ---- chunk-fused split-bf16 HMMA, C = A @ W^T (+bias) ----------------------
// 256 threads, 8 warps of 64x64, CTA tile 256x128. Per 32-K chunk, loads the
// hi AND lo tiles once and issues all 3 split products (Ah*Wh+Ah*Wl+Al*Wh)
// before the next barrier: 24 syncs (vs 72), 2/3 global traffic, 3x ILP.
// smem: A[2][2][256][40] + W[2][2][128][40] bf16 = 122880 B.
#define HN_SMEM 122880
template <int EPI>
__global__ void __launch_bounds__(256) hmma_nt(
    const __nv_bfloat16* __restrict__ Ah, const __nv_bfloat16* __restrict__ Al,
    const __nv_bfloat16* __restrict__ Wh, const __nv_bfloat16* __restrict__ Wl,
    const float* __restrict__ bias, float* __restrict__ out) {
  extern __shared__ char dsm[];
  typedef __nv_bfloat16 AT[2][256][40];  // [hl][row][col]
  typedef __nv_bfloat16 WT[2][128][40];
  AT* As = (AT*)dsm;              // As[stage][hl][r][c]; stage stride 40960 B
  WT* Ws = (WT*)(dsm + 81920);    // Ws[stage][hl][r][c]; stage stride 20480 B
  const int tid = threadIdx.x;
  const int wid = tid >> 5, lane = tid & 31;
  const int n0 = blockIdx.x * 128, m0 = blockIdx.y * 256;
  const int wm = (wid >> 1) * 64, wn = (wid & 1) * 64;
  const int NIT = 24;  // 24 chunks of K=32 (K=768)

  float acc[4][8][4];
#pragma unroll
  for (int i = 0; i < 4; ++i)
#pragma unroll
    for (int j = 0; j < 8; ++j)
#pragma unroll
      for (int z = 0; z < 4; ++z) acc[i][j][z] = 0.f;

  uint32_t a_base[4], w_base[4];
#pragma unroll
  for (int i = 0; i < 4; ++i)
    a_base[i] =
        smem_u32(&As[0][0][wm + i * 16 + (lane & 15)][(lane >> 4) * 8]);
#pragma unroll
  for (int j = 0; j < 4; ++j)
    w_base[j] =
        smem_u32(&Ws[0][0][wn + j * 16 + (lane & 15)][(lane >> 4) * 8]);

  const int lr = tid >> 2, lq = (tid & 3) * 8;
  int arow[4], wrow[2];
#pragma unroll
  for (int i = 0; i < 4; ++i) {
    const int r = m0 + lr + i * 64;
    arow[i] = r < M_ ? r : M_ - 1;
  }
#pragma unroll
  for (int i = 0; i < 2; ++i) wrow[i] = n0 + lr + i * 64;

  uint4 rah[4], ral[4], rwh[2], rwl[2];
#pragma unroll
  for (int i = 0; i < 4; ++i) {
    rah[i] = *(const uint4*)(Ah + (size_t)arow[i] * C_ + lq);
    ral[i] = *(const uint4*)(Al + (size_t)arow[i] * C_ + lq);
  }
#pragma unroll
  for (int i = 0; i < 2; ++i) {
    rwh[i] = *(const uint4*)(Wh + (size_t)wrow[i] * C_ + lq);
    rwl[i] = *(const uint4*)(Wl + (size_t)wrow[i] * C_ + lq);
  }
#pragma unroll
  for (int i = 0; i < 4; ++i) {
    *(uint4*)&As[0][0][lr + i * 64][lq] = rah[i];
    *(uint4*)&As[0][1][lr + i * 64][lq] = ral[i];
  }
#pragma unroll
  for (int i = 0; i < 2; ++i) {
    *(uint4*)&Ws[0][0][lr + i * 64][lq] = rwh[i];
    *(uint4*)&Ws[0][1][lr + i * 64][lq] = rwl[i];
  }
  __syncthreads();

  for (int it = 0; it < NIT; ++it) {
    const int cur = it & 1;
    const bool more = (it + 1) < NIT;
    if (more) {
      const int kc = (it + 1) * 32;
#pragma unroll
      for (int i = 0; i < 4; ++i) {
        rah[i] = *(const uint4*)(Ah + (size_t)arow[i] * C_ + kc + lq);
        ral[i] = *(const uint4*)(Al + (size_t)arow[i] * C_ + kc + lq);
      }
#pragma unroll
      for (int i = 0; i < 2; ++i) {
        rwh[i] = *(const uint4*)(Wh + (size_t)wrow[i] * C_ + kc + lq);
        rwl[i] = *(const uint4*)(Wl + (size_t)wrow[i] * C_ + kc + lq);
      }
    }
    const uint32_t soA = cur * 40960u, soW = cur * 20480u;
#pragma unroll
    for (int p = 0; p < 3; ++p) {
      const uint32_t aoff = soA + ((p == 2) ? 20480u : 0u);
      const uint32_t woff = soW + ((p == 1) ? 10240u : 0u);
#pragma unroll
      for (int s = 0; s < 2; ++s) {
        uint32_t a[4][4], b[4][4];
#pragma unroll
        for (int i = 0; i < 4; ++i) ldsm4(a[i], a_base[i] + aoff + s * 32);
#pragma unroll
        for (int j = 0; j < 4; ++j) ldsm4(b[j], w_base[j] + woff + s * 32);
#pragma unroll
        for (int i = 0; i < 4; ++i)
#pragma unroll
          for (int j = 0; j < 4; ++j) {
            mma16816(acc[i][j * 2], a[i], b[j][0], b[j][2]);
            mma16816(acc[i][j * 2 + 1], a[i], b[j][1], b[j][3]);
          }
      }
    }
    if (more) {
      const int nxt = cur ^ 1;
#pragma unroll
      for (int i = 0; i < 4; ++i) {
        *(uint4*)&As[nxt][0][lr + i * 64][lq] = rah[i];
        *(uint4*)&As[nxt][1][lr + i * 64][lq] = ral[i];
      }
#pragma unroll
      for (int i = 0; i < 2; ++i) {
        *(uint4*)&Ws[nxt][0][lr + i * 64][lq] = rwh[i];
        *(uint4*)&Ws[nxt][1][lr + i * 64][lq] = rwl[i];
      }
    }
    __syncthreads();
  }

  const int g = lane >> 2, tq = lane & 3;
  float* basep = nullptr;
  if (EPI == 0) {
    const int t3 = n0 / C_;
    basep = (t3 == 0) ? g_q : (t3 == 1) ? g_k : g_v;
  }
#pragma unroll
  for (int i = 0; i < 4; ++i) {
    const int r0g = m0 + wm + i * 16 + g;
    const int r1g = r0g + 8;
    int b0i = 0, n0i = 0, b1i = 0, n1i = 0;
    if (EPI == 0) {
      b0i = r0g / N_; n0i = r0g % N_;
      b1i = r1g / N_; n1i = r1g % N_;
    }
#pragma unroll
    for (int j8 = 0; j8 < 8; ++j8) {
      const int cg = n0 + wn + j8 * 8 + 2 * tq;
      const float bb0 = bias[cg], bb1 = bias[cg + 1];
      const float v0 = acc[i][j8][0] + bb0, v1 = acc[i][j8][1] + bb1;
      const float v2 = acc[i][j8][2] + bb0, v3 = acc[i][j8][3] + bb1;
      if (EPI == 0) {
        const int hh = (cg >> 6) % H_;
        const int dd = cg & 63;
        if (r0g < M_)
          *(float2*)(basep +
                     (((size_t)(b0i * H_ + hh) * N_ + n0i) * D_ + dd)) =
              make_float2(v0, v1);
        if (r1g < M_)
          *(float2*)(basep +
                     (((size_t)(b1i * H_ + hh) * N_ + n1i) * D_ + dd)) =
              make_float2(v2, v3);
      } else {
        if (r0g < M_)
          *(float2*)(out + (size_t)r0g * C_ + cg) = make_float2(v0, v1);
        if (r1g < M_)
          *(float2*)(out + (size_t)r1g * C_ + cg) = make_float2(v2, v3);
      }
    }
  }
}

// ---- chunk-fused gauss HMMA: C = exp(-(an+bn-2*A@B^T)/tau), per bh ---------
// smem: A[2][2][128][40] + B[2][2][128][40] = 81920 B (dynamic).
#define GS_SMEM 81920
template <int OUT>
__global__ void __launch_bounds__(256) gauss_hmma(
    const __nv_bfloat16* __restrict__ Ah, const __nv_bfloat16* __restrict__ Al,
    size_t aBS, const __nv_bfloat16* __restrict__ Bh,
    const __nv_bfloat16* __restrict__ Bl, size_t bBS,
    const float* __restrict__ an, int anBS, const float* __restrict__ bn,
    int bnBS, float* __restrict__ Cm, __nv_bfloat16* __restrict__ Oh,
    __nv_bfloat16* __restrict__ Ol, size_t cBS, int ldc) {
  extern __shared__ char gsm[];
  typedef __nv_bfloat16 GT[2][128][40];
  GT* As = (GT*)gsm;              // stage stride 20480 B, hl stride 10240 B
  GT* Bs = (GT*)(gsm + 40960);
  const int tid = threadIdx.x;
  const int wid = tid >> 5, lane = tid & 31;
  const int bh = blockIdx.z;
  const int m0 = blockIdx.y * 128, n0 = blockIdx.x * 128;
  const int wm = (wid >> 1) * 32, wn = (wid & 1) * 64;
  const int NIT = 2;  // K=64, chunks of 32

  float acc[2][8][4];
#pragma unroll
  for (int i = 0; i < 2; ++i)
#pragma unroll
    for (int j = 0; j < 8; ++j)
#pragma unroll
      for (int z = 0; z < 4; ++z) acc[i][j][z] = 0.f;

  uint32_t a_base[2], b_base[4];
#pragma unroll
  for (int i = 0; i < 2; ++i)
    a_base[i] =
        smem_u32(&As[0][0][wm + i * 16 + (lane & 15)][(lane >> 4) * 8]);
#pragma unroll
  for (int j = 0; j < 4; ++j)
    b_base[j] =
        smem_u32(&Bs[0][0][wn + j * 16 + (lane & 15)][(lane >> 4) * 8]);

  const int lr = tid >> 2, lq = (tid & 3) * 8;
  const __nv_bfloat16* AgH = Ah + (size_t)bh * aBS + (size_t)m0 * 64;
  const __nv_bfloat16* AgL = Al + (size_t)bh * aBS + (size_t)m0 * 64;
  const __nv_bfloat16* BgH = Bh + (size_t)bh * bBS + (size_t)n0 * 64;
  const __nv_bfloat16* BgL = Bl + (size_t)bh * bBS + (size_t)n0 * 64;

  uint4 rah[2], ral[2], rbh[2], rbl[2];
#pragma unroll
  for (int i = 0; i < 2; ++i) {
    rah[i] = *(const uint4*)(AgH + (size_t)(lr + i * 64) * 64 + lq);
    ral[i] = *(const uint4*)(AgL + (size_t)(lr + i * 64) * 64 + lq);
    rbh[i] = *(const uint4*)(BgH + (size_t)(lr + i * 64) * 64 + lq);
    rbl[i] = *(const uint4*)(BgL + (size_t)(lr + i * 64) * 64 + lq);
  }
#pragma unroll
  for (int i = 0; i < 2; ++i) {
    *(uint4*)&As[0][0][lr + i * 64][lq] = rah[i];
    *(uint4*)&As[0][1][lr + i * 64][lq] = ral[i];
    *(uint4*)&Bs[0][0][lr + i * 64][lq] = rbh[i];
    *(uint4*)&Bs[0][1][lr + i * 64][lq] = rbl[i];
  }
  __syncthreads();

  for (int it = 0; it < NIT; ++it) {
    const int cur = it & 1;
    const bool more = (it + 1) < NIT;
    if (more) {
      const int kc = (it + 1) * 32;
#pragma unroll
      for (int i = 0; i < 2; ++i) {
        rah[i] = *(const uint4*)(AgH + (size_t)(lr + i * 64) * 64 + kc + lq);
        ral[i] = *(const uint4*)(AgL + (size_t)(lr + i * 64) * 64 + kc + lq);
        rbh[i] = *(const uint4*)(BgH + (size_t)(lr + i * 64) * 64 + kc + lq);
        rbl[i] = *(const uint4*)(BgL + (size_t)(lr + i * 64) * 64 + kc + lq);
      }
    }
    const uint32_t so = cur * 20480u;
#pragma unroll
    for (int p = 0; p < 3; ++p) {
      const uint32_t aoff = so + ((p == 2) ? 10240u : 0u);
      const uint32_t boff = so + ((p == 1) ? 10240u : 0u);
#pragma unroll
      for (int s = 0; s < 2; ++s) {
        uint32_t a[2][4], b[4][4];
#pragma unroll
        for (int i = 0; i < 2; ++i) ldsm4(a[i], a_base[i] + aoff + s * 32);
#pragma unroll
        for (int j = 0; j < 4; ++j) ldsm4(b[j], b_base[j] + boff + s * 32);
#pragma unroll
        for (int i = 0; i < 2; ++i)
#pragma unroll
          for (int j = 0; j < 4; ++j) {
            mma16816(acc[i][j * 2], a[i], b[j][0], b[j][2]);
            mma16816(acc[i][j * 2 + 1], a[i], b[j][1], b[j][3]);
          }
      }
    }
    if (more) {
      const int nxt = cur ^ 1;
#pragma unroll
      for (int i = 0; i < 2; ++i) {
        *(uint4*)&As[nxt][0][lr + i * 64][lq] = rah[i];
        *(uint4*)&As[nxt][1][lr + i * 64][lq] = ral[i];
        *(uint4*)&Bs[nxt][0][lr + i * 64][lq] = rbh[i];
        *(uint4*)&Bs[nxt][1][lr + i * 64][lq] = rbl[i];
      }
    }
    __syncthreads();
  }

  const int g = lane >> 2, tq = lane & 3;
  const float* anp = an + (size_t)bh * anBS;
  const float* bnp = bn + (size_t)bh * bnBS;
#pragma unroll
  for (int i = 0; i < 2; ++i) {
    const int r0 = m0 + wm + i * 16 + g;
    const int r1 = r0 + 8;
    const float an0 = anp[r0], an1 = anp[r1];
#pragma unroll
    for (int j8 = 0; j8 < 8; ++j8) {
      const int cg = n0 + wn + j8 * 8 + 2 * tq;
      const float bn0 = bnp[cg], bn1 = bnp[cg + 1];
      const float e0 = __expf(-(an0 + bn0 - 2.f * acc[i][j8][0]) * TAUINV);
      const float e1 = __expf(-(an0 + bn1 - 2.f * acc[i][j8][1]) * TAUINV);
      const float e2 = __expf(-(an1 + bn0 - 2.f * acc[i][j8][2]) * TAUINV);
      const float e3 = __expf(-(an1 + bn1 - 2.f * acc[i][j8][3]) * TAUINV);
      const size_t ba = (size_t)bh * cBS + (size_t)r0 * ldc + cg;
      const size_t bb = (size_t)bh * cBS + (size_t)r1 * ldc + cg;
      if (OUT == 0) {
        *(float2*)(Cm + ba) = make_float2(e0, e1);
        *(float2*)(Cm + bb) = make_float2(e2, e3);
      } else {
        __nv_bfloat16 h0, l0, h1, l1;
        split2(e0, h0, l0);
        split2(e1, h1, l1);
        __nv_bfloat162 hp, lp;
        hp.x = h0; hp.y = h1; lp.x = l0; lp.y = l1;
        *(__nv_bfloat162*)(Oh + ba) = hp;
        *(__nv_bfloat162*)(Ol + ba) = lp;
        split2(e2, h0, l0);
        split2(e3, h1, l1);
        hp.x = h0; hp.y = h1; lp.x = l0; lp.y = l1;
        *(__nv_bfloat162*)(Oh + bb) = hp;
        *(__nv_bfloat162*)(Ol + bb) = lp;
      }
    }
  }
}

// ---- pipelined warp-MMA bf16 GEMM: C(256x256)=A@B, batched over bh ----------
template <int MODE, int PASSES>
__global__ void __launch_bounds__(256) tm_gemm(
    const __nv_bfloat16* __restrict__ Ah, const __nv_bfloat16* __restrict__ Al,
    const __nv_bfloat16* __restrict__ Bh, const __nv_bfloat16* __restrict__ Bl,
    __nv_bfloat16* __restrict__ Oh, __nv_bfloat16* __restrict__ Ol) {
  __shared__ __align__(16) __nv_bfloat16 As[2][128][40];
  __shared__ __align__(16) __nv_bfloat16 Bs[2][32][136];
  const int tid = threadIdx.x;
  const int wid = tid >> 5, lane = tid & 31;
  const int m0 = blockIdx.y * 128, n0 = blockIdx.x * 128;
  const size_t boff = (size_t)blockIdx.z << 16;
  const int wm = (wid >> 1) * 32, wn = (wid & 1) * 64;
  const int NIT = PASSES * 8;

  float acc[2][8][4];
#pragma unroll
  for (int i = 0; i < 2; ++i)
#pragma unroll
    for (int j = 0; j < 8; ++j)
#pragma unroll
      for (int z = 0; z < 4; ++z) acc[i][j][z] = 0.f;

  uint32_t a_base[2], b_base[4];
#pragma unroll
  for (int i = 0; i < 2; ++i)
    a_base[i] = smem_u32(&As[0][wm + i * 16 + (lane & 15)][(lane >> 4) * 8]);
  {
    const int krow = (lane & 7) + ((lane >> 3) & 1) * 8;
#pragma unroll
    for (int j = 0; j < 4; ++j)
      b_base[j] = smem_u32(&Bs[0][krow][wn + j * 16 + (lane >> 4) * 8]);
  }

  const int arow = tid >> 2, aq = (tid & 3) * 8;
  const int brow = tid >> 4, bq = (tid & 15) * 8;
  const __nv_bfloat16* AgH = Ah + boff + (size_t)m0 * 256;
  const __nv_bfloat16* AgL = (PASSES == 3) ? (Al + boff + (size_t)m0 * 256)
                                           : nullptr;
  const __nv_bfloat16* BgH = Bh + boff + n0;
  const __nv_bfloat16* BgL = (PASSES == 3) ? (Bl + boff + n0) : nullptr;

  uint4 ra[2], rb[2];
  ra[0] = *(const uint4*)(AgH + (size_t)arow * 256 + aq);
  ra[1] = *(const uint4*)(AgH + (size_t)(arow + 64) * 256 + aq);
  rb[0] = *(const uint4*)(BgH + (size_t)brow * 256 + bq);
  rb[1] = *(const uint4*)(BgH + (size_t)(brow + 16) * 256 + bq);
  *(uint4*)&As[0][arow][aq] = ra[0];
  *(uint4*)&As[0][arow + 64][aq] = ra[1];
  *(uint4*)&Bs[0][brow][bq] = rb[0];
  *(uint4*)&Bs[0][brow + 16][bq] = rb[1];
  __syncthreads();

  for (int it = 0; it < NIT; ++it) {
    const int cur = it & 1;
    const bool more = (it + 1) < NIT;
    if (more) {
      const int nit = it + 1;
      const int pass = nit >> 3;
      const int kc = (nit & 7) * 32;
      const __nv_bfloat16* Ap = (PASSES == 3 && pass == 2) ? AgL : AgH;
      const __nv_bfloat16* Bp = (PASSES == 3 && pass == 1) ? BgL : BgH;
      ra[0] = *(const uint4*)(Ap + (size_t)arow * 256 + kc + aq);
      ra[1] = *(const uint4*)(Ap + (size_t)(arow + 64) * 256 + kc + aq);
      rb[0] = *(const uint4*)(Bp + (size_t)(kc + brow) * 256 + bq);
      rb[1] = *(const uint4*)(Bp + (size_t)(kc + brow + 16) * 256 + bq);
    }
    const uint32_t soA = cur * 10240, soB = cur * 8704;
#pragma unroll
    for (int s = 0; s < 2; ++s) {
      uint32_t a[2][4], b[4][4];
#pragma unroll
      for (int i = 0; i < 2; ++i) ldsm4(a[i], a_base[i] + soA + s * 32);
#pragma unroll
      for (int j = 0; j < 4; ++j) ldsm4t(b[j], b_base[j] + soB + s * 4352);
#pragma unroll
      for (int i = 0; i < 2; ++i)
#pragma unroll
        for (int j = 0; j < 4; ++j) {
          mma16816(acc[i][j * 2], a[i], b[j][0], b[j][1]);
          mma16816(acc[i][j * 2 + 1], a[i], b[j][2], b[j][3]);
        }
    }
    if (more) {
      const int nxt = cur ^ 1;
      *(uint4*)&As[nxt][arow][aq] = ra[0];
      *(uint4*)&As[nxt][arow + 64][aq] = ra[1];
      *(uint4*)&Bs[nxt][brow][bq] = rb[0];
      *(uint4*)&Bs[nxt][brow + 16][bq] = rb[1];
    }
    __syncthreads();
  }

  const int g = lane >> 2, tq = lane & 3;
#pragma unroll
  for (int i = 0; i < 2; ++i) {
    const int r0g = m0 + wm + i * 16 + g;
#pragma unroll
    for (int j8 = 0; j8 < 8; ++j8) {
      const int cg = n0 + wn + j8 * 8 + 2 * tq;
      float v0 = acc[i][j8][0], v1 = acc[i][j8][1];
      float v2 = acc[i][j8][2], v3 = acc[i][j8][3];
      if (MODE == 1) {
        v0 = ((r0g == cg) ? 2.f : 0.f) - v0;
        v1 = ((r0g == cg + 1) ? 2.f : 0.f) - v1;
        v2 = ((r0g + 8 == cg) ? 2.f : 0.f) - v2;
        v3 = ((r0g + 8 == cg + 1) ? 2.f : 0.f) - v3;
      }
      const size_t ba = boff + (size_t)r0g * 256 + cg;
      const size_t bb = boff + (size_t)(r0g + 8) * 256 + cg;
      __nv_bfloat16 h0, l0, h1, l1;
      split2(v0, h0, l0);
      split2(v1, h1, l1);
      __nv_bfloat162 hp, lp;
      hp.x = h0; hp.y = h1; lp.x = l0; lp.y = l1;
      *(__nv_bfloat162*)(Oh + ba) = hp;
      *(__nv_bfloat162*)(Ol + ba) = lp;
      split2(v2, h0, l0);
      split2(v3, h1, l1);
      hp.x = h0; hp.y = h1; lp.x = l0; lp.y = l1;
      *(__nv_bfloat162*)(Oh + bb) = hp;
      *(__nv_bfloat162*)(Ol + bb) = lp;
    }
  }
}

// ---- skinny split-2 HMMA: C[M x 64] = A[M x K] @ B[K x 64], batched bh -----
template <int EPI>
__global__ void __launch_bounds__(128) hmma_skinny(
    const __nv_bfloat16* __restrict__ Ah, const __nv_bfloat16* __restrict__ Al,
    size_t aBS, int lda, const __nv_bfloat16* __restrict__ Bh,
    const __nv_bfloat16* __restrict__ Bl, size_t bBS,
    __nv_bfloat16* __restrict__ Oh, __nv_bfloat16* __restrict__ Ol,
    float* __restrict__ Of, size_t oBS, size_t ofBS, int K) {
  __shared__ __align__(16) __nv_bfloat16 As[2][128][40];
  __shared__ __align__(16) __nv_bfloat16 Bs[2][32][72];
  const int tid = threadIdx.x;
  const int wid = tid >> 5, lane = tid & 31;
  const int m0 = blockIdx.x * 128;
  const int bh = blockIdx.y;
  const int wm = wid * 32;
  const int CH = K >> 5;
  const int NIT = 3 * CH;

  float acc[2][8][4];
#pragma unroll
  for (int i = 0; i < 2; ++i)
#pragma unroll
    for (int j = 0; j < 8; ++j)
#pragma unroll
      for (int z = 0; z < 4; ++z) acc[i][j][z] = 0.f;

  uint32_t a_base[2], b_base[4];
#pragma unroll
  for (int i = 0; i < 2; ++i)
    a_base[i] = smem_u32(&As[0][wm + i * 16 + (lane & 15)][(lane >> 4) * 8]);
  {
    const int krow = (lane & 7) + ((lane >> 3) & 1) * 8;
#pragma unroll
    for (int j = 0; j < 4; ++j)
      b_base[j] = smem_u32(&Bs[0][krow][j * 16 + (lane >> 4) * 8]);
  }

  const int ar = tid >> 2, aq = (tid & 3) * 8;
  const int br = tid >> 3, bq = (tid & 7) * 8;
  const __nv_bfloat16* AgH = Ah + (size_t)bh * aBS + (size_t)m0 * lda;
  const __nv_bfloat16* AgL = Al + (size_t)bh * aBS + (size_t)m0 * lda;
  const __nv_bfloat16* BgH = Bh + (size_t)bh * bBS;
  const __nv_bfloat16* BgL = Bl + (size_t)bh * bBS;

  uint4 ra[4], rb[2];
#pragma unroll
  for (int i = 0; i < 4; ++i)
    ra[i] = *(const uint4*)(AgH + (size_t)(ar + i * 32) * lda + aq);
#pragma unroll
  for (int i = 0; i < 2; ++i)
    rb[i] = *(const uint4*)(BgH + (size_t)(br + i * 16) * 64 + bq);
#pragma unroll
  for (int i = 0; i < 4; ++i) *(uint4*)&As[0][ar + i * 32][aq] = ra[i];
#pragma unroll
  for (int i = 0; i < 2; ++i) *(uint4*)&Bs[0][br + i * 16][bq] = rb[i];
  __syncthreads();

  for (int it = 0; it < NIT; ++it) {
    const int cur = it & 1;
    const bool more = (it + 1) < NIT;
    if (more) {
      const int nit = it + 1;
      const int pass = nit / CH;
      const int kc = (nit - pass * CH) * 32;
      const __nv_bfloat16* Ap = (pass == 2) ? AgL : AgH;
      const __nv_bfloat16* Bp = (pass == 1) ? BgL : BgH;
#pragma unroll
      for (int i = 0; i < 4; ++i)
        ra[i] = *(const uint4*)(Ap + (size_t)(ar + i * 32) * lda + kc + aq);
#pragma unroll
      for (int i = 0; i < 2; ++i)
        rb[i] = *(const uint4*)(Bp + (size_t)(kc + br + i * 16) * 64 + bq);
    }
    const uint32_t soA = cur * 10240, soB = cur * 4608;
#pragma unroll
    for (int s = 0; s < 2; ++s) {
      uint32_t a[2][4], b[4][4];
#pragma unroll
      for (int i = 0; i < 2; ++i) ldsm4(a[i], a_base[i] + soA + s * 32);
#pragma unroll
      for (int j = 0; j < 4; ++j) ldsm4t(b[j], b_base[j] + soB + s * 2304);
#pragma unroll
      for (int i = 0; i < 2; ++i)
#pragma unroll
        for (int j = 0; j < 4; ++j) {
          mma16816(acc[i][j * 2], a[i], b[j][0], b[j][1]);
          mma16816(acc[i][j * 2 + 1], a[i], b[j][2], b[j][3]);
        }
    }
    if (more) {
      const int nxt = cur ^ 1;
#pragma unroll
      for (int i = 0; i < 4; ++i) *(uint4*)&As[nxt][ar + i * 32][aq] = ra[i];
#pragma unroll
      for (int i = 0; i < 2; ++i) *(uint4*)&Bs[nxt][br + i * 16][bq] = rb[i];
    }
    __syncthreads();
  }

  const int g = lane >> 2, tq = lane & 3;
#pragma unroll
  for (int i = 0; i < 2; ++i) {
    const int r0 = m0 + wm + i * 16 + g;
    const int r1 = r0 + 8;
#pragma unroll
    for (int j8 = 0; j8 < 8; ++j8) {
      const int cg = j8 * 8 + 2 * tq;
      const float v0 = acc[i][j8][0], v1 = acc[i][j8][1];
      const float v2 = acc[i][j8][2], v3 = acc[i][j8][3];
      if (EPI == 2) {
        float* ob = Of + (size_t)bh * ofBS;
        *(float2*)(ob + (size_t)r0 * 64 + cg) = make_float2(v0, v1);
        *(float2*)(ob + (size_t)r1 * 64 + cg) = make_float2(v2, v3);
      } else {
        const size_t ba = (size_t)bh * oBS + (size_t)r0 * 64 + cg;
        const size_t bb = (size_t)bh * oBS + (size_t)r1 * 64 + cg;
        __nv_bfloat16 h0, l0, h1, l1;
        split2(v0, h0, l0);
        split2(v1, h1, l1);
        __nv_bfloat162 hp, lp;
        hp.x = h0; hp.y = h1; lp.x = l0; lp.y = l1;
        *(__nv_bfloat162*)(Oh + ba) = hp;
        *(__nv_bfloat162*)(Ol + ba) = lp;
        split2(v2, h0, l0);
        split2(v3, h1, l1);
        hp.x = h0; hp.y = h1; lp.x = l0; lp.y = l1;
        *(__nv_bfloat162*)(Oh + bb) = hp;
        *(__nv_bfloat162*)(Ol + bb) = lp;
        if (EPI == 1) {
          float* ob = Of + (size_t)bh * oBS;
          *(float2*)(ob + (size_t)r0 * 64 + cg) = make_float2(v0, v1);
          *(float2*)(ob + (size_t)r1 * 64 + cg) = make_float2(v2, v3);
        }
      }
    }
  }
}

// ------- 2x2 pooling of q/k patches; fp32 + split-bf16 landmark outputs -----
__global__ void pool_kernel() {
  const int bh = blockIdx.x;
  const float* src =
      ((blockIdx.y == 0) ? g_q : g_k) + (size_t)bh * N_ * D_ + D_;
  float* dst = ((blockIdx.y == 0) ? g_qland : g_kland) + (size_t)bh * L_ * D_;
  __nv_bfloat16* dh = ((blockIdx.y == 0) ? g_qlh : g_klh) + (size_t)bh * L_ * D_;
  __nv_bfloat16* dl = ((blockIdx.y == 0) ? g_qll : g_kll) + (size_t)bh * L_ * D_;
  const int d = threadIdx.x;
  for (int l = threadIdx.y; l < L_; l += 4) {
    const int lr = l >> 4, lc = l & 15;
    const int p = (lr * 2) * 32 + lc * 2;
    float s = src[(size_t)p * D_ + d] + src[(size_t)(p + 1) * D_ + d] +
              src[(size_t)(p + 32) * D_ + d] + src[(size_t)(p + 33) * D_ + d];
    s *= 0.25f;
    dst[(size_t)l * D_ + d] = s;
    split2(s, dh[(size_t)l * D_ + d], dl[(size_t)l * D_ + d]);
  }
}

// ---------------- inf-norm of M2 (max over rows of abs row-sum) -------------
__global__ void norminf_kernel() {
  const int bh = blockIdx.x;
  const float* M = g_M2 + (size_t)bh * L_ * L_;
  const int tid = threadIdx.x;
  const int lane = tid & 31, w = tid >> 5;
  __shared__ float wmax[8];
  float mymax = 0.f;
  for (int r = 0; r < 32; ++r) {
    const int row = w * 32 + r;
    const float* p = M + (size_t)row * L_;
    float s = 0.f;
#pragma unroll
    for (int c = 0; c < 8; ++c) s += fabsf(p[lane + c * 32]);
#pragma unroll
    for (int o = 16; o; o >>= 1) s += __shfl_xor_sync(0xffffffffu, s, o);
    mymax = fmaxf(mymax, s);
  }
  if (lane == 0) wmax[w] = mymax;
  __syncthreads();
  if (tid == 0) {
    float m = 0.f;
#pragma unroll
    for (int i = 0; i < 8; ++i) m = fmaxf(m, wmax[i]);
    g_normv[bh] = m;
  }
}

// --- Newton init: split M2 (row-major) and inv0 = M2^T * sc (split) ---------
__global__ void newton_init_split() {
  __shared__ float t[32][33];
  const int bh = blockIdx.z;
  const int x0 = blockIdx.x * 32, y0 = blockIdx.y * 32;
  const int tx = threadIdx.x, ty = threadIdx.y;
  const float* M = g_M2 + (size_t)bh * L_ * L_;
  const float v = M[(size_t)(y0 + ty) * L_ + x0 + tx];
  t[ty][tx] = v;
  const size_t didx = (size_t)bh * L_ * L_ + (size_t)(y0 + ty) * L_ + x0 + tx;
  split2(v, g_Mh[didx], g_Ml[didx]);
  __syncthreads();
  const float nv = g_normv[bh];
  const float sc = 1.f / (nv * nv + 1e-6f);
  const float w = t[tx][ty];
  const size_t tidx = (size_t)bh * L_ * L_ + (size_t)(x0 + ty) * L_ + y0 + tx;
  split2(w * sc, g_IhA[tidx], g_IlA[tidx]);
}

// ---------------- cls-token gauss vector (qcn computed inline) --------------
__global__ void cls_gauss_kernel() {
  const int bh = blockIdx.x;
  __shared__ float qc[64];
  __shared__ float qcn_s;
  const int tid = threadIdx.x;
  if (tid < 64) qc[tid] = g_q[(size_t)bh * N_ * D_ + tid];
  __syncthreads();
  if (tid < 32) {
    float s = qc[tid] * qc[tid] + qc[tid + 32] * qc[tid + 32];
#pragma unroll
    for (int o = 16; o; o >>= 1) s += __shfl_xor_sync(0xffffffffu, s, o);
    if (tid == 0) qcn_s = s;
  }
  __syncthreads();
  const float* kl = g_kland + (size_t)bh * L_ * D_ + (size_t)tid * D_;
  float dot = 0.f;
#pragma unroll
  for (int d = 0; d < 64; d += 4) {
    float4 kv = *(const float4*)(kl + d);
    dot += qc[d] * kv.x + qc[d + 1] * kv.y + qc[d + 2] * kv.z +
           qc[d + 3] * kv.w;
  }
  float dist = qcn_s + g_kln[(size_t)bh * L_ + tid] - 2.f * dot;
  g_Mcls[(size_t)bh * L_ + tid] = __expf(-dist * TAUINV);
}

// ---------------- y_cls = Mcls @ V_mixed ------------------------------------
__global__ void ycls_kernel() {
  const int bh = blockIdx.x;
  __shared__ float mc[256];
  const int tid = threadIdx.x;
  mc[tid] = g_Mcls[(size_t)bh * L_ + tid];
  __syncthreads();
  if (tid < 64) {
    const float* vm = g_Vm + (size_t)bh * L_ * D_ + tid;
    float s = 0.f;
    for (int k = 0; k < L_; ++k) s += mc[k] * vm[(size_t)k * D_];
    g_y[(size_t)bh * N_ * D_ + tid] = s;
  }
}

// ---------------- host orchestration ----------------------------------------
extern "C" void kernel_launch(void* const* d_in, const int* in_sizes, int n_in,
                              void* d_out, int out_size) {
  (void)in_sizes; (void)n_in; (void)out_size;
  const float* x = (const float*)d_in[0];
  const float* qkv_w = (const float*)d_in[1];
  const float* qkv_b = (const float*)d_in[2];
  const float* proj_w = (const float*)d_in[3];
  const float* proj_b = (const float*)d_in[4];
  float* out = (float*)d_out;

  float *p_q, *p_k, *p_v, *p_qn, *p_kn, *p_qln, *p_kln, *p_M2, *p_Vm, *p_y;
  cudaGetSymbolAddress((void**)&p_q, g_q);
  cudaGetSymbolAddress((void**)&p_k, g_k);
  cudaGetSymbolAddress((void**)&p_v, g_v);
  cudaGetSymbolAddress((void**)&p_y, g_y);
  cudaGetSymbolAddress((void**)&p_qn, g_qn);
  cudaGetSymbolAddress((void**)&p_kn, g_kn);
  cudaGetSymbolAddress((void**)&p_qln, g_qln);
  cudaGetSymbolAddress((void**)&p_kln, g_kln);
  cudaGetSymbolAddress((void**)&p_M2, g_M2);
  cudaGetSymbolAddress((void**)&p_Vm, g_Vm);

  __nv_bfloat16 *p_Mh, *p_Ml, *p_T1h, *p_T1l;
  __nv_bfloat16 *p_IhA, *p_IlA, *p_IhB, *p_IlB;
  __nv_bfloat16 *p_Xh, *p_Xl, *p_Wqh, *p_Wql, *p_Pwh, *p_Pwl, *p_Yh, *p_Yl;
  __nv_bfloat16 *p_M1h, *p_M1l, *p_M3h, *p_M3l;
  __nv_bfloat16 *p_qph, *p_qpl, *p_kph, *p_kpl, *p_vph, *p_vpl;
  __nv_bfloat16 *p_qlh, *p_qll, *p_klh, *p_kll;
  __nv_bfloat16 *p_KVh, *p_KVl, *p_Vmh, *p_Vml;
  cudaGetSymbolAddress((void**)&p_Mh, g_Mh);
  cudaGetSymbolAddress((void**)&p_Ml, g_Ml);
  cudaGetSymbolAddress((void**)&p_T1h, g_T1h);
  cudaGetSymbolAddress((void**)&p_T1l, g_T1l);
  cudaGetSymbolAddress((void**)&p_IhA, g_IhA);
  cudaGetSymbolAddress((void**)&p_IlA, g_IlA);
  cudaGetSymbolAddress((void**)&p_IhB, g_IhB);
  cudaGetSymbolAddress((void**)&p_IlB, g_IlB);
  cudaGetSymbolAddress((void**)&p_Xh, g_Xh);
  cudaGetSymbolAddress((void**)&p_Xl, g_Xl);
  cudaGetSymbolAddress((void**)&p_Wqh, g_Wqh);
  cudaGetSymbolAddress((void**)&p_Wql, g_Wql);
  cudaGetSymbolAddress((void**)&p_Pwh, g_Pwh);
  cudaGetSymbolAddress((void**)&p_Pwl, g_Pwl);
  cudaGetSymbolAddress((void**)&p_Yh, g_Yh);
  cudaGetSymbolAddress((void**)&p_Yl, g_Yl);
  cudaGetSymbolAddress((void**)&p_M1h, g_M1h);
  cudaGetSymbolAddress((void**)&p_M1l, g_M1l);
  cudaGetSymbolAddress((void**)&p_M3h, g_M3h);
  cudaGetSymbolAddress((void**)&p_M3l, g_M3l);
  cudaGetSymbolAddress((void**)&p_qph, g_qph);
  cudaGetSymbolAddress((void**)&p_qpl, g_qpl);
  cudaGetSymbolAddress((void**)&p_kph, g_kph);
  cudaGetSymbolAddress((void**)&p_kpl, g_kpl);
  cudaGetSymbolAddress((void**)&p_vph, g_vph);
  cudaGetSymbolAddress((void**)&p_vpl, g_vpl);
  cudaGetSymbolAddress((void**)&p_qlh, g_qlh);
  cudaGetSymbolAddress((void**)&p_qll, g_qll);
  cudaGetSymbolAddress((void**)&p_klh, g_klh);
  cudaGetSymbolAddress((void**)&p_kll, g_kll);
  cudaGetSymbolAddress((void**)&p_KVh, g_KVh);
  cudaGetSymbolAddress((void**)&p_KVl, g_KVl);
  cudaGetSymbolAddress((void**)&p_Vmh, g_Vmh);
  cudaGetSymbolAddress((void**)&p_Vml, g_Vml);

  cudaFuncSetAttribute(hmma_nt<0>,
                       cudaFuncAttributeMaxDynamicSharedMemorySize, HN_SMEM);
  cudaFuncSetAttribute(hmma_nt<1>,
                       cudaFuncAttributeMaxDynamicSharedMemorySize, HN_SMEM);
  cudaFuncSetAttribute(gauss_hmma<0>,
                       cudaFuncAttributeMaxDynamicSharedMemorySize, GS_SMEM);
  cudaFuncSetAttribute(gauss_hmma<1>,
                       cudaFuncAttributeMaxDynamicSharedMemorySize, GS_SMEM);

  // 0) split projection operands
  {
    const int nx4 = M_ * C_ / 4;
    split_kernel<<<(nx4 + 255) / 256, 256>>>(
        (const float4*)x, (__nv_bfloat162*)p_Xh, (__nv_bfloat162*)p_Xl, nx4);
    const int nw4 = 3 * C_ * C_ / 4;
    split_kernel<<<(nw4 + 255) / 256, 256>>>(
        (const float4*)qkv_w, (__nv_bfloat162*)p_Wqh, (__nv_bfloat162*)p_Wql,
        nw4);
    const int np4 = C_ * C_ / 4;
    split_kernel<<<(np4 + 255) / 256, 256>>>(
        (const float4*)proj_w, (__nv_bfloat162*)p_Pwh, (__nv_bfloat162*)p_Pwl,
        np4);
  }
  // 1) QKV projection (chunk-fused split HMMA)
  hmma_nt<0><<<dim3(18, 65), 256, HN_SMEM>>>(p_Xh, p_Xl, p_Wqh, p_Wql, qkv_b,
                                             nullptr);
  // 2) landmarks + fused patch splits (+ row norms for q,k)
  pool_kernel<<<dim3(BH_, 2), dim3(64, 4)>>>();
  vsplit_norm<<<BH_ * NP_ / 8, 256>>>(p_q, (__nv_bfloat162*)p_qph,
                                      (__nv_bfloat162*)p_qpl, p_qn);
  vsplit_norm<<<BH_ * NP_ / 8, 256>>>(p_k, (__nv_bfloat162*)p_kph,
                                      (__nv_bfloat162*)p_kpl, p_kn);
  vsplit_norm<<<BH_ * NP_ / 8, 256>>>(p_v, (__nv_bfloat162*)p_vph,
                                      (__nv_bfloat162*)p_vpl, nullptr);
  land_norm<<<dim3(BH_, 2), 256>>>();
  // 4) Gaussian kernel matrices via chunk-fused split HMMA
  gauss_hmma<1><<<dim3(2, 8, BH_), 256, GS_SMEM>>>(
      p_qph, p_qpl, (size_t)NP_ * D_, p_klh, p_kll, (size_t)L_ * D_, p_qn, NP_,
      p_kln, L_, nullptr, p_M1h, p_M1l, (size_t)NP_ * L_, L_);
  gauss_hmma<0><<<dim3(2, 2, BH_), 256, GS_SMEM>>>(
      p_qlh, p_qll, (size_t)L_ * D_, p_klh, p_kll, (size_t)L_ * D_, p_qln, L_,
      p_kln, L_, p_M2, nullptr, nullptr, (size_t)L_ * L_, L_);
  gauss_hmma<1><<<dim3(8, 2, BH_), 256, GS_SMEM>>>(
      p_qlh, p_qll, (size_t)L_ * D_, p_kph, p_kpl, (size_t)NP_ * D_, p_qln, L_,
      p_kn, NP_, nullptr, p_M3h, p_M3l, (size_t)L_ * NP_, NP_);
  cls_gauss_kernel<<<BH_, 256>>>();
  // 5) Newton-Schulz: 4 plain-bf16 + 2 split-2 iterations
  norminf_kernel<<<BH_, 256>>>();
  newton_init_split<<<dim3(8, 8, BH_), dim3(32, 32)>>>();
  __nv_bfloat16 *invH, *invL;
  {
    __nv_bfloat16 *Ih = p_IhA, *Il = p_IlA;
    __nv_bfloat16 *nIh = p_IhB, *nIl = p_IlB;
    const dim3 tg(2, 2, BH_);
    for (int it = 0; it < 4; ++it) {
      tm_gemm<1, 1><<<tg, 256>>>(p_Mh, nullptr, Ih, nullptr, p_T1h, p_T1l);
      tm_gemm<0, 1><<<tg, 256>>>(Ih, nullptr, p_T1h, nullptr, nIh, nIl);
      __nv_bfloat16* t;
      t = Ih; Ih = nIh; nIh = t;
      t = Il; Il = nIl; nIl = t;
    }
    tm_gemm<1, 3><<<tg, 256>>>(p_Mh, p_Ml, Ih, Il, p_T1h, p_T1l);
    tm_gemm<0, 3><<<tg, 256>>>(Ih, Il, p_T1h, p_T1l, nIh, nIl);
    {
      __nv_bfloat16* t;
      t = Ih; Ih = nIh; nIh = t;
      t = Il; Il = nIl; nIl = t;
    }
    tm_gemm<1, 3><<<tg, 256>>>(p_Mh, p_Ml, Ih, Il, p_T1h, p_T1l);
    tm_gemm<0, 3><<<tg, 256>>>(Ih, Il, p_T1h, p_T1l, nIh, nIl);
    invH = nIh; invL = nIl;
  }
  // 6) V_mixed = inv @ (M3 @ v_patch)
  hmma_skinny<0><<<dim3(2, BH_), 128>>>(
      p_M3h, p_M3l, (size_t)L_ * NP_, NP_, p_vph, p_vpl, (size_t)NP_ * D_,
      p_KVh, p_KVl, nullptr, (size_t)L_ * D_, 0, NP_);
  hmma_skinny<1><<<dim3(2, BH_), 128>>>(
      invH, invL, (size_t)L_ * L_, L_, p_KVh, p_KVl, (size_t)L_ * D_, p_Vmh,
      p_Vml, p_Vm, (size_t)L_ * D_, 0, L_);
  // 7) y = [y_cls; M1 @ V_mixed]
  hmma_skinny<2><<<dim3(8, BH_), 128>>>(
      p_M1h, p_M1l, (size_t)NP_ * L_, L_, p_Vmh, p_Vml, (size_t)L_ * D_,
      nullptr, nullptr, p_y + D_, 0, (size_t)N_ * D_, L_);
  ycls_kernel<<<BH_, 256>>>();
  // 8) output projection
  ysplit_kernel<<<dim3(3, M_), 256>>>(p_Yh, p_Yl);
  hmma_nt<1><<<dim3(6, 65), 256, HN_SMEM>>>(p_Yh, p_Yl, p_Pwh, p_Pwl, proj_b,
                                            out);
}

// round 16
// speedup vs baseline: 1.0499x; 1.0499x over previous
#include <cuda_runtime.h>
#include <cuda_bf16.h>
#include <math.h>
#include <stdint.h>

#define B_ 16
#define N_ 1025
#define C_ 768
#define H_ 12
#define D_ 64
#define NP_ 1024
#define L_ 256
#define BH_ 192
#define M_ 16400
#define TAUINV 0.125f

// ---------------- scratch (device globals; no runtime allocation) -----------
__device__ float g_q[(size_t)BH_ * N_ * D_];
__device__ float g_k[(size_t)BH_ * N_ * D_];
__device__ float g_v[(size_t)BH_ * N_ * D_];
__device__ float g_qland[(size_t)BH_ * L_ * D_];
__device__ float g_kland[(size_t)BH_ * L_ * D_];
__device__ float g_qn[(size_t)BH_ * NP_];
__device__ float g_kn[(size_t)BH_ * NP_];
__device__ float g_qln[(size_t)BH_ * L_];
__device__ float g_kln[(size_t)BH_ * L_];
__device__ float g_M2[(size_t)BH_ * L_ * L_];
__device__ float g_normv[BH_];
__device__ float g_Vm[(size_t)BH_ * L_ * D_];
__device__ float g_Mcls[(size_t)BH_ * L_];

#define LL_ ((size_t)BH_ * L_ * L_)
__device__ __nv_bfloat16 g_Mh[LL_], g_Ml[LL_];
__device__ __nv_bfloat16 g_T1h[LL_], g_T1l[LL_];
__device__ __nv_bfloat16 g_IhA[LL_], g_IlA[LL_];
__device__ __nv_bfloat16 g_IhB[LL_], g_IlB[LL_];

__device__ __nv_bfloat16 g_M1h[(size_t)BH_ * NP_ * L_], g_M1l[(size_t)BH_ * NP_ * L_];
__device__ __nv_bfloat16 g_M3h[(size_t)BH_ * L_ * NP_], g_M3l[(size_t)BH_ * L_ * NP_];
__device__ __nv_bfloat16 g_qph[(size_t)BH_ * NP_ * D_], g_qpl[(size_t)BH_ * NP_ * D_];
__device__ __nv_bfloat16 g_kph[(size_t)BH_ * NP_ * D_], g_kpl[(size_t)BH_ * NP_ * D_];
__device__ __nv_bfloat16 g_vph[(size_t)BH_ * NP_ * D_], g_vpl[(size_t)BH_ * NP_ * D_];
__device__ __nv_bfloat16 g_qlh[(size_t)BH_ * L_ * D_], g_qll[(size_t)BH_ * L_ * D_];
__device__ __nv_bfloat16 g_klh[(size_t)BH_ * L_ * D_], g_kll[(size_t)BH_ * L_ * D_];
__device__ __nv_bfloat16 g_KVh[(size_t)BH_ * L_ * D_], g_KVl[(size_t)BH_ * L_ * D_];
__device__ __nv_bfloat16 g_Vmh[(size_t)BH_ * L_ * D_], g_Vml[(size_t)BH_ * L_ * D_];

__device__ __nv_bfloat16 g_Xh[(size_t)M_ * C_], g_Xl[(size_t)M_ * C_];
__device__ __nv_bfloat16 g_Wqh[(size_t)3 * C_ * C_], g_Wql[(size_t)3 * C_ * C_];
__device__ __nv_bfloat16 g_Pwh[(size_t)C_ * C_], g_Pwl[(size_t)C_ * C_];
__device__ __nv_bfloat16 g_Yh[(size_t)M_ * C_], g_Yl[(size_t)M_ * C_];

// ======================= warp-MMA helpers ====================================
__device__ __forceinline__ uint32_t smem_u32(const void* p) {
  uint32_t a;
  asm("{ .reg .u64 t; cvta.to.shared.u64 t, %1; cvt.u32.u64 %0, t; }"
      : "=r"(a) : "l"(p));
  return a;
}
__device__ __forceinline__ void ldsm4(uint32_t* r, uint32_t addr) {
  asm volatile(
      "ldmatrix.sync.aligned.m8n8.x4.shared.b16 {%0,%1,%2,%3}, [%4];"
      : "=r"(r[0]), "=r"(r[1]), "=r"(r[2]), "=r"(r[3]) : "r"(addr));
}
__device__ __forceinline__ void ldsm4t(uint32_t* r, uint32_t addr) {
  asm volatile(
      "ldmatrix.sync.aligned.m8n8.x4.trans.shared.b16 {%0,%1,%2,%3}, [%4];"
      : "=r"(r[0]), "=r"(r[1]), "=r"(r[2]), "=r"(r[3]) : "r"(addr));
}
__device__ __forceinline__ void mma16816(float* c, const uint32_t* a,
                                         const uint32_t b0, const uint32_t b1) {
  asm volatile(
      "mma.sync.aligned.m16n8k16.row.col.f32.bf16.bf16.f32 "
      "{%0,%1,%2,%3}, {%4,%5,%6,%7}, {%8,%9}, {%0,%1,%2,%3};"
      : "+f"(c[0]), "+f"(c[1]), "+f"(c[2]), "+f"(c[3])
      : "r"(a[0]), "r"(a[1]), "r"(a[2]), "r"(a[3]), "r"(b0), "r"(b1));
}
__device__ __forceinline__ void split2(float v, __nv_bfloat16& h,
                                       __nv_bfloat16& l) {
  h = __float2bfloat16(v);
  l = __float2bfloat16(v - __bfloat162float(h));
}

// ---------------- generic fp32 -> split-bf16 --------------------------------
__global__ void split_kernel(const float4* __restrict__ in,
                             __nv_bfloat162* __restrict__ h2,
                             __nv_bfloat162* __restrict__ l2, int n4) {
  const int i = blockIdx.x * 256 + threadIdx.x;
  if (i >= n4) return;
  float4 v = in[i];
  __nv_bfloat16 hx, lx, hy, ly;
  split2(v.x, hx, lx);
  split2(v.y, hy, ly);
  __nv_bfloat162 hp, lp;
  hp.x = hx; hp.y = hy; lp.x = lx; lp.y = ly;
  h2[i * 2] = hp;
  l2[i * 2] = lp;
  split2(v.z, hx, lx);
  split2(v.w, hy, ly);
  hp.x = hx; hp.y = hy; lp.x = lx; lp.y = ly;
  h2[i * 2 + 1] = hp;
  l2[i * 2 + 1] = lp;
}

// ---- patch split (warp per row) + optional row sum-of-squares (fused) ------
__global__ void vsplit_norm(const float* __restrict__ src,
                            __nv_bfloat162* __restrict__ vh,
                            __nv_bfloat162* __restrict__ vl,
                            float* __restrict__ norm) {
  const int row = blockIdx.x * 8 + (threadIdx.x >> 5);
  const int lane = threadIdx.x & 31;
  const int bh = row >> 10, r = row & 1023;
  const float2 v = *(const float2*)(src + (size_t)bh * N_ * D_ + D_ +
                                    (size_t)r * D_ + lane * 2);
  __nv_bfloat16 hx, lx, hy, ly;
  split2(v.x, hx, lx);
  split2(v.y, hy, ly);
  __nv_bfloat162 hp, lp;
  hp.x = hx; hp.y = hy; lp.x = lx; lp.y = ly;
  vh[(size_t)row * 32 + lane] = hp;
  vl[(size_t)row * 32 + lane] = lp;
  if (norm) {
    float s = v.x * v.x + v.y * v.y;
#pragma unroll
    for (int o = 16; o; o >>= 1) s += __shfl_xor_sync(0xffffffffu, s, o);
    if (lane == 0) norm[(size_t)bh * NP_ + r] = s;
  }
}

// ---- landmark row norms: one launch for qln and kln ------------------------
__global__ void land_norm() {
  const int bh = blockIdx.x;
  const float* src =
      ((blockIdx.y == 0) ? g_qland : g_kland) + (size_t)bh * L_ * D_;
  float* out = ((blockIdx.y == 0) ? g_qln : g_kln) + (size_t)bh * L_;
  const int w = threadIdx.x >> 5, lane = threadIdx.x & 31;
  for (int r = w; r < L_; r += 8) {
    const float* p = src + (size_t)r * D_;
    float v0 = p[lane], v1 = p[lane + 32];
    float s = v0 * v0 + v1 * v1;
#pragma unroll
    for (int o = 16; o; o >>= 1) s += __shfl_xor_sync(0xffffffffu, s, o);
    if (lane == 0) out[r] = s;
  }
}

// ---- pipelined split-bf16 HMMA, C = A @ W^T (+bias) — R14 best config ------
// 256 threads, 8 warps of 64x64, CTA tile 256x128, register double-buffer.
#define HN_SMEM 61440
template <int EPI>
__global__ void __launch_bounds__(256) hmma_nt(
    const __nv_bfloat16* __restrict__ Ah, const __nv_bfloat16* __restrict__ Al,
    const __nv_bfloat16* __restrict__ Wh, const __nv_bfloat16* __restrict__ Wl,
    const float* __restrict__ bias, float* __restrict__ out) {
  extern __shared__ char dsm[];
  typedef __nv_bfloat16 ArowT[256][40];
  typedef __nv_bfloat16 WrowT[128][40];
  ArowT* As = (ArowT*)dsm;
  WrowT* Ws = (WrowT*)(dsm + 40960);
  const int tid = threadIdx.x;
  const int wid = tid >> 5, lane = tid & 31;
  const int n0 = blockIdx.x * 128, m0 = blockIdx.y * 256;
  const int wm = (wid >> 1) * 64, wn = (wid & 1) * 64;
  const int NIT = 72;

  float acc[4][8][4];
#pragma unroll
  for (int i = 0; i < 4; ++i)
#pragma unroll
    for (int j = 0; j < 8; ++j)
#pragma unroll
      for (int z = 0; z < 4; ++z) acc[i][j][z] = 0.f;

  uint32_t a_base[4], w_base[4];
#pragma unroll
  for (int i = 0; i < 4; ++i)
    a_base[i] = smem_u32(&As[0][wm + i * 16 + (lane & 15)][(lane >> 4) * 8]);
#pragma unroll
  for (int j = 0; j < 4; ++j)
    w_base[j] = smem_u32(&Ws[0][wn + j * 16 + (lane & 15)][(lane >> 4) * 8]);

  const int lr = tid >> 2, lq = (tid & 3) * 8;
  int arow[4], wrow[2];
#pragma unroll
  for (int i = 0; i < 4; ++i) {
    const int r = m0 + lr + i * 64;
    arow[i] = r < M_ ? r : M_ - 1;
  }
#pragma unroll
  for (int i = 0; i < 2; ++i) wrow[i] = n0 + lr + i * 64;

  uint4 ra[4], rw[2];
#pragma unroll
  for (int i = 0; i < 4; ++i)
    ra[i] = *(const uint4*)(Ah + (size_t)arow[i] * C_ + lq);
#pragma unroll
  for (int i = 0; i < 2; ++i)
    rw[i] = *(const uint4*)(Wh + (size_t)wrow[i] * C_ + lq);
#pragma unroll
  for (int i = 0; i < 4; ++i) *(uint4*)&As[0][lr + i * 64][lq] = ra[i];
#pragma unroll
  for (int i = 0; i < 2; ++i) *(uint4*)&Ws[0][lr + i * 64][lq] = rw[i];
  __syncthreads();

  for (int it = 0; it < NIT; ++it) {
    const int cur = it & 1;
    const bool more = (it + 1) < NIT;
    if (more) {
      const int nit = it + 1;
      const int pass = nit / 24;
      const int kc = (nit - pass * 24) * 32;
      const __nv_bfloat16* Ap = (pass == 2) ? Al : Ah;
      const __nv_bfloat16* Wp = (pass == 1) ? Wl : Wh;
#pragma unroll
      for (int i = 0; i < 4; ++i)
        ra[i] = *(const uint4*)(Ap + (size_t)arow[i] * C_ + kc + lq);
#pragma unroll
      for (int i = 0; i < 2; ++i)
        rw[i] = *(const uint4*)(Wp + (size_t)wrow[i] * C_ + kc + lq);
    }
    const uint32_t soA = cur * 20480, soW = cur * 10240;
#pragma unroll
    for (int s = 0; s < 2; ++s) {
      uint32_t a[4][4], b[4][4];
#pragma unroll
      for (int i = 0; i < 4; ++i) ldsm4(a[i], a_base[i] + soA + s * 32);
#pragma unroll
      for (int j = 0; j < 4; ++j) ldsm4(b[j], w_base[j] + soW + s * 32);
#pragma unroll
      for (int i = 0; i < 4; ++i)
#pragma unroll
        for (int j = 0; j < 4; ++j) {
          mma16816(acc[i][j * 2], a[i], b[j][0], b[j][2]);
          mma16816(acc[i][j * 2 + 1], a[i], b[j][1], b[j][3]);
        }
    }
    if (more) {
      const int nxt = cur ^ 1;
#pragma unroll
      for (int i = 0; i < 4; ++i) *(uint4*)&As[nxt][lr + i * 64][lq] = ra[i];
#pragma unroll
      for (int i = 0; i < 2; ++i) *(uint4*)&Ws[nxt][lr + i * 64][lq] = rw[i];
    }
    __syncthreads();
  }

  const int g = lane >> 2, tq = lane & 3;
  float* basep = nullptr;
  if (EPI == 0) {
    const int t3 = n0 / C_;
    basep = (t3 == 0) ? g_q : (t3 == 1) ? g_k : g_v;
  }
#pragma unroll
  for (int i = 0; i < 4; ++i) {
    const int r0g = m0 + wm + i * 16 + g;
    const int r1g = r0g + 8;
    int b0i = 0, n0i = 0, b1i = 0, n1i = 0;
    if (EPI == 0) {
      b0i = r0g / N_; n0i = r0g % N_;
      b1i = r1g / N_; n1i = r1g % N_;
    }
#pragma unroll
    for (int j8 = 0; j8 < 8; ++j8) {
      const int cg = n0 + wn + j8 * 8 + 2 * tq;
      const float bb0 = bias[cg], bb1 = bias[cg + 1];
      const float v0 = acc[i][j8][0] + bb0, v1 = acc[i][j8][1] + bb1;
      const float v2 = acc[i][j8][2] + bb0, v3 = acc[i][j8][3] + bb1;
      if (EPI == 0) {
        const int hh = (cg >> 6) % H_;
        const int dd = cg & 63;
        if (r0g < M_)
          *(float2*)(basep +
                     (((size_t)(b0i * H_ + hh) * N_ + n0i) * D_ + dd)) =
              make_float2(v0, v1);
        if (r1g < M_)
          *(float2*)(basep +
                     (((size_t)(b1i * H_ + hh) * N_ + n1i) * D_ + dd)) =
              make_float2(v2, v3);
      } else {
        if (r0g < M_)
          *(float2*)(out + (size_t)r0g * C_ + cg) = make_float2(v0, v1);
        if (r1g < M_)
          *(float2*)(out + (size_t)r1g * C_ + cg) = make_float2(v2, v3);
      }
    }
  }
}

// ---- gauss HMMA (R14 best config): C = exp(-(an+bn-2*A@B^T)/tau) -----------
template <int OUT>
__global__ void __launch_bounds__(256) gauss_hmma(
    const __nv_bfloat16* __restrict__ Ah, const __nv_bfloat16* __restrict__ Al,
    size_t aBS, const __nv_bfloat16* __restrict__ Bh,
    const __nv_bfloat16* __restrict__ Bl, size_t bBS,
    const float* __restrict__ an, int anBS, const float* __restrict__ bn,
    int bnBS, float* __restrict__ Cm, __nv_bfloat16* __restrict__ Oh,
    __nv_bfloat16* __restrict__ Ol, size_t cBS, int ldc) {
  __shared__ __align__(16) __nv_bfloat16 As[2][128][40];
  __shared__ __align__(16) __nv_bfloat16 Bs[2][128][40];
  const int tid = threadIdx.x;
  const int wid = tid >> 5, lane = tid & 31;
  const int bh = blockIdx.z;
  const int m0 = blockIdx.y * 128, n0 = blockIdx.x * 128;
  const int wm = (wid >> 1) * 32, wn = (wid & 1) * 64;
  const int NIT = 6;

  float acc[2][8][4];
#pragma unroll
  for (int i = 0; i < 2; ++i)
#pragma unroll
    for (int j = 0; j < 8; ++j)
#pragma unroll
      for (int z = 0; z < 4; ++z) acc[i][j][z] = 0.f;

  uint32_t a_base[2], b_base[4];
#pragma unroll
  for (int i = 0; i < 2; ++i)
    a_base[i] = smem_u32(&As[0][wm + i * 16 + (lane & 15)][(lane >> 4) * 8]);
#pragma unroll
  for (int j = 0; j < 4; ++j)
    b_base[j] = smem_u32(&Bs[0][wn + j * 16 + (lane & 15)][(lane >> 4) * 8]);

  const int lr = tid >> 2, lq = (tid & 3) * 8;
  const __nv_bfloat16* AgH = Ah + (size_t)bh * aBS + (size_t)m0 * 64;
  const __nv_bfloat16* AgL = Al + (size_t)bh * aBS + (size_t)m0 * 64;
  const __nv_bfloat16* BgH = Bh + (size_t)bh * bBS + (size_t)n0 * 64;
  const __nv_bfloat16* BgL = Bl + (size_t)bh * bBS + (size_t)n0 * 64;

  uint4 ra[2], rb[2];
#pragma unroll
  for (int i = 0; i < 2; ++i) {
    ra[i] = *(const uint4*)(AgH + (size_t)(lr + i * 64) * 64 + lq);
    rb[i] = *(const uint4*)(BgH + (size_t)(lr + i * 64) * 64 + lq);
  }
#pragma unroll
  for (int i = 0; i < 2; ++i) {
    *(uint4*)&As[0][lr + i * 64][lq] = ra[i];
    *(uint4*)&Bs[0][lr + i * 64][lq] = rb[i];
  }
  __syncthreads();

  for (int it = 0; it < NIT; ++it) {
    const int cur = it & 1;
    const bool more = (it + 1) < NIT;
    if (more) {
      const int nit = it + 1;
      const int pass = nit >> 1;
      const int kc = (nit & 1) * 32;
      const __nv_bfloat16* Ap = (pass == 2) ? AgL : AgH;
      const __nv_bfloat16* Bp = (pass == 1) ? BgL : BgH;
#pragma unroll
      for (int i = 0; i < 2; ++i) {
        ra[i] = *(const uint4*)(Ap + (size_t)(lr + i * 64) * 64 + kc + lq);
        rb[i] = *(const uint4*)(Bp + (size_t)(lr + i * 64) * 64 + kc + lq);
      }
    }
    const uint32_t so = cur * 10240;
#pragma unroll
    for (int s = 0; s < 2; ++s) {
      uint32_t a[2][4], b[4][4];
#pragma unroll
      for (int i = 0; i < 2; ++i) ldsm4(a[i], a_base[i] + so + s * 32);
#pragma unroll
      for (int j = 0; j < 4; ++j) ldsm4(b[j], b_base[j] + so + s * 32);
#pragma unroll
      for (int i = 0; i < 2; ++i)
#pragma unroll
        for (int j = 0; j < 4; ++j) {
          mma16816(acc[i][j * 2], a[i], b[j][0], b[j][2]);
          mma16816(acc[i][j * 2 + 1], a[i], b[j][1], b[j][3]);
        }
    }
    if (more) {
      const int nxt = cur ^ 1;
#pragma unroll
      for (int i = 0; i < 2; ++i) {
        *(uint4*)&As[nxt][lr + i * 64][lq] = ra[i];
        *(uint4*)&Bs[nxt][lr + i * 64][lq] = rb[i];
      }
    }
    __syncthreads();
  }

  const int g = lane >> 2, tq = lane & 3;
  const float* anp = an + (size_t)bh * anBS;
  const float* bnp = bn + (size_t)bh * bnBS;
#pragma unroll
  for (int i = 0; i < 2; ++i) {
    const int r0 = m0 + wm + i * 16 + g;
    const int r1 = r0 + 8;
    const float an0 = anp[r0], an1 = anp[r1];
#pragma unroll
    for (int j8 = 0; j8 < 8; ++j8) {
      const int cg = n0 + wn + j8 * 8 + 2 * tq;
      const float bn0 = bnp[cg], bn1 = bnp[cg + 1];
      const float e0 = __expf(-(an0 + bn0 - 2.f * acc[i][j8][0]) * TAUINV);
      const float e1 = __expf(-(an0 + bn1 - 2.f * acc[i][j8][1]) * TAUINV);
      const float e2 = __expf(-(an1 + bn0 - 2.f * acc[i][j8][2]) * TAUINV);
      const float e3 = __expf(-(an1 + bn1 - 2.f * acc[i][j8][3]) * TAUINV);
      const size_t ba = (size_t)bh * cBS + (size_t)r0 * ldc + cg;
      const size_t bb = (size_t)bh * cBS + (size_t)r1 * ldc + cg;
      if (OUT == 0) {
        *(float2*)(Cm + ba) = make_float2(e0, e1);
        *(float2*)(Cm + bb) = make_float2(e2, e3);
      } else {
        __nv_bfloat16 h0, l0, h1, l1;
        split2(e0, h0, l0);
        split2(e1, h1, l1);
        __nv_bfloat162 hp, lp;
        hp.x = h0; hp.y = h1; lp.x = l0; lp.y = l1;
        *(__nv_bfloat162*)(Oh + ba) = hp;
        *(__nv_bfloat162*)(Ol + ba) = lp;
        split2(e2, h0, l0);
        split2(e3, h1, l1);
        hp.x = h0; hp.y = h1; lp.x = l0; lp.y = l1;
        *(__nv_bfloat162*)(Oh + bb) = hp;
        *(__nv_bfloat162*)(Ol + bb) = lp;
      }
    }
  }
}

// ---- pipelined warp-MMA bf16 GEMM: C(256x256)=A@B, batched over bh ----------
template <int MODE, int PASSES>
__global__ void __launch_bounds__(256) tm_gemm(
    const __nv_bfloat16* __restrict__ Ah, const __nv_bfloat16* __restrict__ Al,
    const __nv_bfloat16* __restrict__ Bh, const __nv_bfloat16* __restrict__ Bl,
    __nv_bfloat16* __restrict__ Oh, __nv_bfloat16* __restrict__ Ol) {
  __shared__ __align__(16) __nv_bfloat16 As[2][128][40];
  __shared__ __align__(16) __nv_bfloat16 Bs[2][32][136];
  const int tid = threadIdx.x;
  const int wid = tid >> 5, lane = tid & 31;
  const int m0 = blockIdx.y * 128, n0 = blockIdx.x * 128;
  const size_t boff = (size_t)blockIdx.z << 16;
  const int wm = (wid >> 1) * 32, wn = (wid & 1) * 64;
  const int NIT = PASSES * 8;

  float acc[2][8][4];
#pragma unroll
  for (int i = 0; i < 2; ++i)
#pragma unroll
    for (int j = 0; j < 8; ++j)
#pragma unroll
      for (int z = 0; z < 4; ++z) acc[i][j][z] = 0.f;

  uint32_t a_base[2], b_base[4];
#pragma unroll
  for (int i = 0; i < 2; ++i)
    a_base[i] = smem_u32(&As[0][wm + i * 16 + (lane & 15)][(lane >> 4) * 8]);
  {
    const int krow = (lane & 7) + ((lane >> 3) & 1) * 8;
#pragma unroll
    for (int j = 0; j < 4; ++j)
      b_base[j] = smem_u32(&Bs[0][krow][wn + j * 16 + (lane >> 4) * 8]);
  }

  const int arow = tid >> 2, aq = (tid & 3) * 8;
  const int brow = tid >> 4, bq = (tid & 15) * 8;
  const __nv_bfloat16* AgH = Ah + boff + (size_t)m0 * 256;
  const __nv_bfloat16* AgL = (PASSES == 3) ? (Al + boff + (size_t)m0 * 256)
                                           : nullptr;
  const __nv_bfloat16* BgH = Bh + boff + n0;
  const __nv_bfloat16* BgL = (PASSES == 3) ? (Bl + boff + n0) : nullptr;

  uint4 ra[2], rb[2];
  ra[0] = *(const uint4*)(AgH + (size_t)arow * 256 + aq);
  ra[1] = *(const uint4*)(AgH + (size_t)(arow + 64) * 256 + aq);
  rb[0] = *(const uint4*)(BgH + (size_t)brow * 256 + bq);
  rb[1] = *(const uint4*)(BgH + (size_t)(brow + 16) * 256 + bq);
  *(uint4*)&As[0][arow][aq] = ra[0];
  *(uint4*)&As[0][arow + 64][aq] = ra[1];
  *(uint4*)&Bs[0][brow][bq] = rb[0];
  *(uint4*)&Bs[0][brow + 16][bq] = rb[1];
  __syncthreads();

  for (int it = 0; it < NIT; ++it) {
    const int cur = it & 1;
    const bool more = (it + 1) < NIT;
    if (more) {
      const int nit = it + 1;
      const int pass = nit >> 3;
      const int kc = (nit & 7) * 32;
      const __nv_bfloat16* Ap = (PASSES == 3 && pass == 2) ? AgL : AgH;
      const __nv_bfloat16* Bp = (PASSES == 3 && pass == 1) ? BgL : BgH;
      ra[0] = *(const uint4*)(Ap + (size_t)arow * 256 + kc + aq);
      ra[1] = *(const uint4*)(Ap + (size_t)(arow + 64) * 256 + kc + aq);
      rb[0] = *(const uint4*)(Bp + (size_t)(kc + brow) * 256 + bq);
      rb[1] = *(const uint4*)(Bp + (size_t)(kc + brow + 16) * 256 + bq);
    }
    const uint32_t soA = cur * 10240, soB = cur * 8704;
#pragma unroll
    for (int s = 0; s < 2; ++s) {
      uint32_t a[2][4], b[4][4];
#pragma unroll
      for (int i = 0; i < 2; ++i) ldsm4(a[i], a_base[i] + soA + s * 32);
#pragma unroll
      for (int j = 0; j < 4; ++j) ldsm4t(b[j], b_base[j] + soB + s * 4352);
#pragma unroll
      for (int i = 0; i < 2; ++i)
#pragma unroll
        for (int j = 0; j < 4; ++j) {
          mma16816(acc[i][j * 2], a[i], b[j][0], b[j][1]);
          mma16816(acc[i][j * 2 + 1], a[i], b[j][2], b[j][3]);
        }
    }
    if (more) {
      const int nxt = cur ^ 1;
      *(uint4*)&As[nxt][arow][aq] = ra[0];
      *(uint4*)&As[nxt][arow + 64][aq] = ra[1];
      *(uint4*)&Bs[nxt][brow][bq] = rb[0];
      *(uint4*)&Bs[nxt][brow + 16][bq] = rb[1];
    }
    __syncthreads();
  }

  const int g = lane >> 2, tq = lane & 3;
#pragma unroll
  for (int i = 0; i < 2; ++i) {
    const int r0g = m0 + wm + i * 16 + g;
#pragma unroll
    for (int j8 = 0; j8 < 8; ++j8) {
      const int cg = n0 + wn + j8 * 8 + 2 * tq;
      float v0 = acc[i][j8][0], v1 = acc[i][j8][1];
      float v2 = acc[i][j8][2], v3 = acc[i][j8][3];
      if (MODE == 1) {
        v0 = ((r0g == cg) ? 2.f : 0.f) - v0;
        v1 = ((r0g == cg + 1) ? 2.f : 0.f) - v1;
        v2 = ((r0g + 8 == cg) ? 2.f : 0.f) - v2;
        v3 = ((r0g + 8 == cg + 1) ? 2.f : 0.f) - v3;
      }
      const size_t ba = boff + (size_t)r0g * 256 + cg;
      const size_t bb = boff + (size_t)(r0g + 8) * 256 + cg;
      __nv_bfloat16 h0, l0, h1, l1;
      split2(v0, h0, l0);
      split2(v1, h1, l1);
      __nv_bfloat162 hp, lp;
      hp.x = h0; hp.y = h1; lp.x = l0; lp.y = l1;
      *(__nv_bfloat162*)(Oh + ba) = hp;
      *(__nv_bfloat162*)(Ol + ba) = lp;
      split2(v2, h0, l0);
      split2(v3, h1, l1);
      hp.x = h0; hp.y = h1; lp.x = l0; lp.y = l1;
      *(__nv_bfloat162*)(Oh + bb) = hp;
      *(__nv_bfloat162*)(Ol + bb) = lp;
    }
  }
}

// ---- skinny split-2 HMMA: C[M x 64] = A[M x K] @ B[K x 64], batched bh -----
// EPI 0: split out (per-bh stride oBS).  EPI 1: split + fp32 (Of per-bh oBS).
// EPI 3: split direct into proj-layout Y (row r -> token r+1, col h*64+cg).
template <int EPI>
__global__ void __launch_bounds__(128) hmma_skinny(
    const __nv_bfloat16* __restrict__ Ah, const __nv_bfloat16* __restrict__ Al,
    size_t aBS, int lda, const __nv_bfloat16* __restrict__ Bh,
    const __nv_bfloat16* __restrict__ Bl, size_t bBS,
    __nv_bfloat16* __restrict__ Oh, __nv_bfloat16* __restrict__ Ol,
    float* __restrict__ Of, size_t oBS, int K) {
  __shared__ __align__(16) __nv_bfloat16 As[2][128][40];
  __shared__ __align__(16) __nv_bfloat16 Bs[2][32][72];
  const int tid = threadIdx.x;
  const int wid = tid >> 5, lane = tid & 31;
  const int m0 = blockIdx.x * 128;
  const int bh = blockIdx.y;
  const int wm = wid * 32;
  const int CH = K >> 5;
  const int NIT = 3 * CH;

  float acc[2][8][4];
#pragma unroll
  for (int i = 0; i < 2; ++i)
#pragma unroll
    for (int j = 0; j < 8; ++j)
#pragma unroll
      for (int z = 0; z < 4; ++z) acc[i][j][z] = 0.f;

  uint32_t a_base[2], b_base[4];
#pragma unroll
  for (int i = 0; i < 2; ++i)
    a_base[i] = smem_u32(&As[0][wm + i * 16 + (lane & 15)][(lane >> 4) * 8]);
  {
    const int krow = (lane & 7) + ((lane >> 3) & 1) * 8;
#pragma unroll
    for (int j = 0; j < 4; ++j)
      b_base[j] = smem_u32(&Bs[0][krow][j * 16 + (lane >> 4) * 8]);
  }

  const int ar = tid >> 2, aq = (tid & 3) * 8;
  const int br = tid >> 3, bq = (tid & 7) * 8;
  const __nv_bfloat16* AgH = Ah + (size_t)bh * aBS + (size_t)m0 * lda;
  const __nv_bfloat16* AgL = Al + (size_t)bh * aBS + (size_t)m0 * lda;
  const __nv_bfloat16* BgH = Bh + (size_t)bh * bBS;
  const __nv_bfloat16* BgL = Bl + (size_t)bh * bBS;

  uint4 ra[4], rb[2];
#pragma unroll
  for (int i = 0; i < 4; ++i)
    ra[i] = *(const uint4*)(AgH + (size_t)(ar + i * 32) * lda + aq);
#pragma unroll
  for (int i = 0; i < 2; ++i)
    rb[i] = *(const uint4*)(BgH + (size_t)(br + i * 16) * 64 + bq);
#pragma unroll
  for (int i = 0; i < 4; ++i) *(uint4*)&As[0][ar + i * 32][aq] = ra[i];
#pragma unroll
  for (int i = 0; i < 2; ++i) *(uint4*)&Bs[0][br + i * 16][bq] = rb[i];
  __syncthreads();

  for (int it = 0; it < NIT; ++it) {
    const int cur = it & 1;
    const bool more = (it + 1) < NIT;
    if (more) {
      const int nit = it + 1;
      const int pass = nit / CH;
      const int kc = (nit - pass * CH) * 32;
      const __nv_bfloat16* Ap = (pass == 2) ? AgL : AgH;
      const __nv_bfloat16* Bp = (pass == 1) ? BgL : BgH;
#pragma unroll
      for (int i = 0; i < 4; ++i)
        ra[i] = *(const uint4*)(Ap + (size_t)(ar + i * 32) * lda + kc + aq);
#pragma unroll
      for (int i = 0; i < 2; ++i)
        rb[i] = *(const uint4*)(Bp + (size_t)(kc + br + i * 16) * 64 + bq);
    }
    const uint32_t soA = cur * 10240, soB = cur * 4608;
#pragma unroll
    for (int s = 0; s < 2; ++s) {
      uint32_t a[2][4], b[4][4];
#pragma unroll
      for (int i = 0; i < 2; ++i) ldsm4(a[i], a_base[i] + soA + s * 32);
#pragma unroll
      for (int j = 0; j < 4; ++j) ldsm4t(b[j], b_base[j] + soB + s * 2304);
#pragma unroll
      for (int i = 0; i < 2; ++i)
#pragma unroll
        for (int j = 0; j < 4; ++j) {
          mma16816(acc[i][j * 2], a[i], b[j][0], b[j][1]);
          mma16816(acc[i][j * 2 + 1], a[i], b[j][2], b[j][3]);
        }
    }
    if (more) {
      const int nxt = cur ^ 1;
#pragma unroll
      for (int i = 0; i < 4; ++i) *(uint4*)&As[nxt][ar + i * 32][aq] = ra[i];
#pragma unroll
      for (int i = 0; i < 2; ++i) *(uint4*)&Bs[nxt][br + i * 16][bq] = rb[i];
    }
    __syncthreads();
  }

  const int g = lane >> 2, tq = lane & 3;
  int ybase = 0, ycol = 0;
  if (EPI == 3) {
    const int b = bh / H_, h = bh % H_;
    ybase = b * N_ + 1;  // token offset for patch row 0
    ycol = h * 64;
  }
#pragma unroll
  for (int i = 0; i < 2; ++i) {
    const int r0 = m0 + wm + i * 16 + g;
    const int r1 = r0 + 8;
#pragma unroll
    for (int j8 = 0; j8 < 8; ++j8) {
      const int cg = j8 * 8 + 2 * tq;
      const float v0 = acc[i][j8][0], v1 = acc[i][j8][1];
      const float v2 = acc[i][j8][2], v3 = acc[i][j8][3];
      if (EPI == 3) {
        const size_t ba = (size_t)(ybase + r0) * C_ + ycol + cg;
        const size_t bb = (size_t)(ybase + r1) * C_ + ycol + cg;
        __nv_bfloat16 h0, l0, h1, l1;
        split2(v0, h0, l0);
        split2(v1, h1, l1);
        __nv_bfloat162 hp, lp;
        hp.x = h0; hp.y = h1; lp.x = l0; lp.y = l1;
        *(__nv_bfloat162*)(g_Yh + ba) = hp;
        *(__nv_bfloat162*)(g_Yl + ba) = lp;
        split2(v2, h0, l0);
        split2(v3, h1, l1);
        hp.x = h0; hp.y = h1; lp.x = l0; lp.y = l1;
        *(__nv_bfloat162*)(g_Yh + bb) = hp;
        *(__nv_bfloat162*)(g_Yl + bb) = lp;
      } else {
        const size_t ba = (size_t)bh * oBS + (size_t)r0 * 64 + cg;
        const size_t bb = (size_t)bh * oBS + (size_t)r1 * 64 + cg;
        __nv_bfloat16 h0, l0, h1, l1;
        split2(v0, h0, l0);
        split2(v1, h1, l1);
        __nv_bfloat162 hp, lp;
        hp.x = h0; hp.y = h1; lp.x = l0; lp.y = l1;
        *(__nv_bfloat162*)(Oh + ba) = hp;
        *(__nv_bfloat162*)(Ol + ba) = lp;
        split2(v2, h0, l0);
        split2(v3, h1, l1);
        hp.x = h0; hp.y = h1; lp.x = l0; lp.y = l1;
        *(__nv_bfloat162*)(Oh + bb) = hp;
        *(__nv_bfloat162*)(Ol + bb) = lp;
        if (EPI == 1) {
          float* ob = Of + (size_t)bh * oBS;
          *(float2*)(ob + (size_t)r0 * 64 + cg) = make_float2(v0, v1);
          *(float2*)(ob + (size_t)r1 * 64 + cg) = make_float2(v2, v3);
        }
      }
    }
  }
}

// ------- 2x2 pooling of q/k patches; fp32 + split-bf16 landmark outputs -----
__global__ void pool_kernel() {
  const int bh = blockIdx.x;
  const float* src =
      ((blockIdx.y == 0) ? g_q : g_k) + (size_t)bh * N_ * D_ + D_;
  float* dst = ((blockIdx.y == 0) ? g_qland : g_kland) + (size_t)bh * L_ * D_;
  __nv_bfloat16* dh = ((blockIdx.y == 0) ? g_qlh : g_klh) + (size_t)bh * L_ * D_;
  __nv_bfloat16* dl = ((blockIdx.y == 0) ? g_qll : g_kll) + (size_t)bh * L_ * D_;
  const int d = threadIdx.x;
  for (int l = threadIdx.y; l < L_; l += 4) {
    const int lr = l >> 4, lc = l & 15;
    const int p = (lr * 2) * 32 + lc * 2;
    float s = src[(size_t)p * D_ + d] + src[(size_t)(p + 1) * D_ + d] +
              src[(size_t)(p + 32) * D_ + d] + src[(size_t)(p + 33) * D_ + d];
    s *= 0.25f;
    dst[(size_t)l * D_ + d] = s;
    split2(s, dh[(size_t)l * D_ + d], dl[(size_t)l * D_ + d]);
  }
}

// ---------------- inf-norm of M2 (max over rows of abs row-sum) -------------
__global__ void norminf_kernel() {
  const int bh = blockIdx.x;
  const float* M = g_M2 + (size_t)bh * L_ * L_;
  const int tid = threadIdx.x;
  const int lane = tid & 31, w = tid >> 5;
  __shared__ float wmax[8];
  float mymax = 0.f;
  for (int r = 0; r < 32; ++r) {
    const int row = w * 32 + r;
    const float* p = M + (size_t)row * L_;
    float s = 0.f;
#pragma unroll
    for (int c = 0; c < 8; ++c) s += fabsf(p[lane + c * 32]);
#pragma unroll
    for (int o = 16; o; o >>= 1) s += __shfl_xor_sync(0xffffffffu, s, o);
    mymax = fmaxf(mymax, s);
  }
  if (lane == 0) wmax[w] = mymax;
  __syncthreads();
  if (tid == 0) {
    float m = 0.f;
#pragma unroll
    for (int i = 0; i < 8; ++i) m = fmaxf(m, wmax[i]);
    g_normv[bh] = m;
  }
}

// --- Newton init: split M2 (row-major) and inv0 = M2^T * sc (split) ---------
__global__ void newton_init_split() {
  __shared__ float t[32][33];
  const int bh = blockIdx.z;
  const int x0 = blockIdx.x * 32, y0 = blockIdx.y * 32;
  const int tx = threadIdx.x, ty = threadIdx.y;
  const float* M = g_M2 + (size_t)bh * L_ * L_;
  const float v = M[(size_t)(y0 + ty) * L_ + x0 + tx];
  t[ty][tx] = v;
  const size_t didx = (size_t)bh * L_ * L_ + (size_t)(y0 + ty) * L_ + x0 + tx;
  split2(v, g_Mh[didx], g_Ml[didx]);
  __syncthreads();
  const float nv = g_normv[bh];
  const float sc = 1.f / (nv * nv + 1e-6f);
  const float w = t[tx][ty];
  const size_t tidx = (size_t)bh * L_ * L_ + (size_t)(x0 + ty) * L_ + y0 + tx;
  split2(w * sc, g_IhA[tidx], g_IlA[tidx]);
}

// ---------------- cls-token gauss vector (qcn computed inline) --------------
__global__ void cls_gauss_kernel() {
  const int bh = blockIdx.x;
  __shared__ float qc[64];
  __shared__ float qcn_s;
  const int tid = threadIdx.x;
  if (tid < 64) qc[tid] = g_q[(size_t)bh * N_ * D_ + tid];
  __syncthreads();
  if (tid < 32) {
    float s = qc[tid] * qc[tid] + qc[tid + 32] * qc[tid + 32];
#pragma unroll
    for (int o = 16; o; o >>= 1) s += __shfl_xor_sync(0xffffffffu, s, o);
    if (tid == 0) qcn_s = s;
  }
  __syncthreads();
  const float* kl = g_kland + (size_t)bh * L_ * D_ + (size_t)tid * D_;
  float dot = 0.f;
#pragma unroll
  for (int d = 0; d < 64; d += 4) {
    float4 kv = *(const float4*)(kl + d);
    dot += qc[d] * kv.x + qc[d + 1] * kv.y + qc[d + 2] * kv.z +
           qc[d + 3] * kv.w;
  }
  float dist = qcn_s + g_kln[(size_t)bh * L_ + tid] - 2.f * dot;
  g_Mcls[(size_t)bh * L_ + tid] = __expf(-dist * TAUINV);
}

// --------- y_cls = Mcls @ V_mixed, written split into Y proj layout ---------
__global__ void ycls_kernel() {
  const int bh = blockIdx.x;
  __shared__ float mc[256];
  const int tid = threadIdx.x;
  mc[tid] = g_Mcls[(size_t)bh * L_ + tid];
  __syncthreads();
  if (tid < 64) {
    const float* vm = g_Vm + (size_t)bh * L_ * D_ + tid;
    float s = 0.f;
    for (int k = 0; k < L_; ++k) s += mc[k] * vm[(size_t)k * D_];
    const int b = bh / H_, h = bh % H_;
    const size_t idx = (size_t)(b * N_) * C_ + h * 64 + tid;
    split2(s, g_Yh[idx], g_Yl[idx]);
  }
}

// ---------------- host orchestration ----------------------------------------
extern "C" void kernel_launch(void* const* d_in, const int* in_sizes, int n_in,
                              void* d_out, int out_size) {
  (void)in_sizes; (void)n_in; (void)out_size;
  const float* x = (const float*)d_in[0];
  const float* qkv_w = (const float*)d_in[1];
  const float* qkv_b = (const float*)d_in[2];
  const float* proj_w = (const float*)d_in[3];
  const float* proj_b = (const float*)d_in[4];
  float* out = (float*)d_out;

  float *p_q, *p_k, *p_v, *p_qn, *p_kn, *p_qln, *p_kln, *p_M2, *p_Vm;
  cudaGetSymbolAddress((void**)&p_q, g_q);
  cudaGetSymbolAddress((void**)&p_k, g_k);
  cudaGetSymbolAddress((void**)&p_v, g_v);
  cudaGetSymbolAddress((void**)&p_qn, g_qn);
  cudaGetSymbolAddress((void**)&p_kn, g_kn);
  cudaGetSymbolAddress((void**)&p_qln, g_qln);
  cudaGetSymbolAddress((void**)&p_kln, g_kln);
  cudaGetSymbolAddress((void**)&p_M2, g_M2);
  cudaGetSymbolAddress((void**)&p_Vm, g_Vm);

  __nv_bfloat16 *p_Mh, *p_Ml, *p_T1h, *p_T1l;
  __nv_bfloat16 *p_IhA, *p_IlA, *p_IhB, *p_IlB;
  __nv_bfloat16 *p_Xh, *p_Xl, *p_Wqh, *p_Wql, *p_Pwh, *p_Pwl, *p_Yh, *p_Yl;
  __nv_bfloat16 *p_M1h, *p_M1l, *p_M3h, *p_M3l;
  __nv_bfloat16 *p_qph, *p_qpl, *p_kph, *p_kpl, *p_vph, *p_vpl;
  __nv_bfloat16 *p_qlh, *p_qll, *p_klh, *p_kll;
  __nv_bfloat16 *p_KVh, *p_KVl, *p_Vmh, *p_Vml;
  cudaGetSymbolAddress((void**)&p_Mh, g_Mh);
  cudaGetSymbolAddress((void**)&p_Ml, g_Ml);
  cudaGetSymbolAddress((void**)&p_T1h, g_T1h);
  cudaGetSymbolAddress((void**)&p_T1l, g_T1l);
  cudaGetSymbolAddress((void**)&p_IhA, g_IhA);
  cudaGetSymbolAddress((void**)&p_IlA, g_IlA);
  cudaGetSymbolAddress((void**)&p_IhB, g_IhB);
  cudaGetSymbolAddress((void**)&p_IlB, g_IlB);
  cudaGetSymbolAddress((void**)&p_Xh, g_Xh);
  cudaGetSymbolAddress((void**)&p_Xl, g_Xl);
  cudaGetSymbolAddress((void**)&p_Wqh, g_Wqh);
  cudaGetSymbolAddress((void**)&p_Wql, g_Wql);
  cudaGetSymbolAddress((void**)&p_Pwh, g_Pwh);
  cudaGetSymbolAddress((void**)&p_Pwl, g_Pwl);
  cudaGetSymbolAddress((void**)&p_Yh, g_Yh);
  cudaGetSymbolAddress((void**)&p_Yl, g_Yl);
  cudaGetSymbolAddress((void**)&p_M1h, g_M1h);
  cudaGetSymbolAddress((void**)&p_M1l, g_M1l);
  cudaGetSymbolAddress((void**)&p_M3h, g_M3h);
  cudaGetSymbolAddress((void**)&p_M3l, g_M3l);
  cudaGetSymbolAddress((void**)&p_qph, g_qph);
  cudaGetSymbolAddress((void**)&p_qpl, g_qpl);
  cudaGetSymbolAddress((void**)&p_kph, g_kph);
  cudaGetSymbolAddress((void**)&p_kpl, g_kpl);
  cudaGetSymbolAddress((void**)&p_vph, g_vph);
  cudaGetSymbolAddress((void**)&p_vpl, g_vpl);
  cudaGetSymbolAddress((void**)&p_qlh, g_qlh);
  cudaGetSymbolAddress((void**)&p_qll, g_qll);
  cudaGetSymbolAddress((void**)&p_klh, g_klh);
  cudaGetSymbolAddress((void**)&p_kll, g_kll);
  cudaGetSymbolAddress((void**)&p_KVh, g_KVh);
  cudaGetSymbolAddress((void**)&p_KVl, g_KVl);
  cudaGetSymbolAddress((void**)&p_Vmh, g_Vmh);
  cudaGetSymbolAddress((void**)&p_Vml, g_Vml);

  cudaFuncSetAttribute(hmma_nt<0>,
                       cudaFuncAttributeMaxDynamicSharedMemorySize, HN_SMEM);
  cudaFuncSetAttribute(hmma_nt<1>,
                       cudaFuncAttributeMaxDynamicSharedMemorySize, HN_SMEM);

  // 0) split projection operands
  {
    const int nx4 = M_ * C_ / 4;
    split_kernel<<<(nx4 + 255) / 256, 256>>>(
        (const float4*)x, (__nv_bfloat162*)p_Xh, (__nv_bfloat162*)p_Xl, nx4);
    const int nw4 = 3 * C_ * C_ / 4;
    split_kernel<<<(nw4 + 255) / 256, 256>>>(
        (const float4*)qkv_w, (__nv_bfloat162*)p_Wqh, (__nv_bfloat162*)p_Wql,
        nw4);
    const int np4 = C_ * C_ / 4;
    split_kernel<<<(np4 + 255) / 256, 256>>>(
        (const float4*)proj_w, (__nv_bfloat162*)p_Pwh, (__nv_bfloat162*)p_Pwl,
        np4);
  }
  // 1) QKV projection (register double-buffered HMMA, R14 config)
  hmma_nt<0><<<dim3(18, 65), 256, HN_SMEM>>>(p_Xh, p_Xl, p_Wqh, p_Wql, qkv_b,
                                             nullptr);
  // 2) landmarks + fused patch splits (+ row norms for q,k)
  pool_kernel<<<dim3(BH_, 2), dim3(64, 4)>>>();
  vsplit_norm<<<BH_ * NP_ / 8, 256>>>(p_q, (__nv_bfloat162*)p_qph,
                                      (__nv_bfloat162*)p_qpl, p_qn);
  vsplit_norm<<<BH_ * NP_ / 8, 256>>>(p_k, (__nv_bfloat162*)p_kph,
                                      (__nv_bfloat162*)p_kpl, p_kn);
  vsplit_norm<<<BH_ * NP_ / 8, 256>>>(p_v, (__nv_bfloat162*)p_vph,
                                      (__nv_bfloat162*)p_vpl, nullptr);
  land_norm<<<dim3(BH_, 2), 256>>>();
  // 4) Gaussian kernel matrices via split-2 HMMA
  gauss_hmma<1><<<dim3(2, 8, BH_), 256>>>(
      p_qph, p_qpl, (size_t)NP_ * D_, p_klh, p_kll, (size_t)L_ * D_, p_qn, NP_,
      p_kln, L_, nullptr, p_M1h, p_M1l, (size_t)NP_ * L_, L_);
  gauss_hmma<0><<<dim3(2, 2, BH_), 256>>>(
      p_qlh, p_qll, (size_t)L_ * D_, p_klh, p_kll, (size_t)L_ * D_, p_qln, L_,
      p_kln, L_, p_M2, nullptr, nullptr, (size_t)L_ * L_, L_);
  gauss_hmma<1><<<dim3(8, 2, BH_), 256>>>(
      p_qlh, p_qll, (size_t)L_ * D_, p_kph, p_kpl, (size_t)NP_ * D_, p_qln, L_,
      p_kn, NP_, nullptr, p_M3h, p_M3l, (size_t)L_ * NP_, NP_);
  cls_gauss_kernel<<<BH_, 256>>>();
  // 5) Newton-Schulz: 4 plain-bf16 + 2 split-2 iterations
  norminf_kernel<<<BH_, 256>>>();
  newton_init_split<<<dim3(8, 8, BH_), dim3(32, 32)>>>();
  __nv_bfloat16 *invH, *invL;
  {
    __nv_bfloat16 *Ih = p_IhA, *Il = p_IlA;
    __nv_bfloat16 *nIh = p_IhB, *nIl = p_IlB;
    const dim3 tg(2, 2, BH_);
    for (int it = 0; it < 4; ++it) {
      tm_gemm<1, 1><<<tg, 256>>>(p_Mh, nullptr, Ih, nullptr, p_T1h, p_T1l);
      tm_gemm<0, 1><<<tg, 256>>>(Ih, nullptr, p_T1h, nullptr, nIh, nIl);
      __nv_bfloat16* t;
      t = Ih; Ih = nIh; nIh = t;
      t = Il; Il = nIl; nIl = t;
    }
    tm_gemm<1, 3><<<tg, 256>>>(p_Mh, p_Ml, Ih, Il, p_T1h, p_T1l);
    tm_gemm<0, 3><<<tg, 256>>>(Ih, Il, p_T1h, p_T1l, nIh, nIl);
    {
      __nv_bfloat16* t;
      t = Ih; Ih = nIh; nIh = t;
      t = Il; Il = nIl; nIl = t;
    }
    tm_gemm<1, 3><<<tg, 256>>>(p_Mh, p_Ml, Ih, Il, p_T1h, p_T1l);
    tm_gemm<0, 3><<<tg, 256>>>(Ih, Il, p_T1h, p_T1l, nIh, nIl);
    invH = nIh; invL = nIl;
  }
  // 6) V_mixed = inv @ (M3 @ v_patch)
  hmma_skinny<0><<<dim3(2, BH_), 128>>>(
      p_M3h, p_M3l, (size_t)L_ * NP_, NP_, p_vph, p_vpl, (size_t)NP_ * D_,
      p_KVh, p_KVl, nullptr, (size_t)L_ * D_, NP_);
  hmma_skinny<1><<<dim3(2, BH_), 128>>>(
      invH, invL, (size_t)L_ * L_, L_, p_KVh, p_KVl, (size_t)L_ * D_, p_Vmh,
      p_Vml, p_Vm, (size_t)L_ * D_, L_);
  // 7) y_patch = M1 @ V_mixed, written split directly into Y proj layout
  hmma_skinny<3><<<dim3(8, BH_), 128>>>(
      p_M1h, p_M1l, (size_t)NP_ * L_, L_, p_Vmh, p_Vml, (size_t)L_ * D_,
      nullptr, nullptr, nullptr, 0, L_);
  ycls_kernel<<<BH_, 256>>>();
  // 8) output projection
  hmma_nt<1><<<dim3(6, 65), 256, HN_SMEM>>>(p_Yh, p_Yl, p_Pwh, p_Pwl, proj_b,
                                            out);
}